// round 2
// baseline (speedup 1.0000x reference)
#include <cuda_runtime.h>
#include <math.h>

// ---------------------------------------------------------------------------
// Encoder_84413287236054 : fp32 transformer encoder layer
// B=2, S=2048, D=1024, H=16, hd=64, DFF=4096
// Round 2: packed fp32x2 (FFMA2) math in GEMM + attention. Exact fp32.
// ---------------------------------------------------------------------------

#define TOK  4096      // B*S
#define DIM  1024
#define DFF  4096
#define NH   16
#define HD   64
#define SEQ  2048
#define BATCH 2

typedef unsigned long long u64;

// ---- packed f32x2 helpers (sm_103a FFMA2 path, PTX-only) -------------------
__device__ __forceinline__ u64 splat2(float x) {
    u64 r; asm("mov.b64 %0,{%1,%1};" : "=l"(r) : "f"(x)); return r;
}
__device__ __forceinline__ void unpk2(u64 v, float& a, float& b) {
    asm("mov.b64 {%0,%1},%2;" : "=f"(a), "=f"(b) : "l"(v));
}
__device__ __forceinline__ u64 ffma2(u64 a, u64 b, u64 c) {
    u64 d; asm("fma.rn.f32x2 %0,%1,%2,%3;" : "=l"(d) : "l"(a), "l"(b), "l"(c));
    return d;
}
__device__ __forceinline__ u64 fmul2(u64 a, u64 b) {
    u64 d; asm("mul.rn.f32x2 %0,%1,%2;" : "=l"(d) : "l"(a), "l"(b));
    return d;
}
__device__ __forceinline__ u64 fadd2(u64 a, u64 b) {
    u64 d; asm("add.rn.f32x2 %0,%1,%2;" : "=l"(d) : "l"(a), "l"(b));
    return d;
}

// Scratch (allocation-free: __device__ globals)
__device__ float g_h   [TOK * DIM];
__device__ float g_q   [TOK * DIM];
__device__ float g_k   [TOK * DIM];
__device__ float g_v   [TOK * DIM];
__device__ float g_attn[TOK * DIM];
__device__ float g_x1  [TOK * DIM];
__device__ float g_h2  [TOK * DIM];
__device__ float g_ff  [TOK * DFF];

// ---------------------------------------------------------------------------
// LayerNorm: one block per row (1024 cols), 256 threads, float4 per thread.
// ---------------------------------------------------------------------------
__global__ __launch_bounds__(256) void ln_kernel(
    const float* __restrict__ x, const float* __restrict__ g,
    const float* __restrict__ b, float* __restrict__ out)
{
    const int row = blockIdx.x;
    const int t = threadIdx.x;
    const float4 v = ((const float4*)(x + (size_t)row * DIM))[t];

    float s  = v.x + v.y + v.z + v.w;
    float ss = v.x*v.x + v.y*v.y + v.z*v.z + v.w*v.w;
    #pragma unroll
    for (int o = 16; o; o >>= 1) {
        s  += __shfl_xor_sync(0xffffffffu, s,  o);
        ss += __shfl_xor_sync(0xffffffffu, ss, o);
    }
    __shared__ float sm[8], sm2[8];
    if ((t & 31) == 0) { sm[t >> 5] = s; sm2[t >> 5] = ss; }
    __syncthreads();
    float ts = 0.f, tss = 0.f;
    #pragma unroll
    for (int i = 0; i < 8; i++) { ts += sm[i]; tss += sm2[i]; }

    const float mu   = ts * (1.0f / DIM);
    const float var  = tss * (1.0f / DIM) - mu * mu;
    const float rstd = rsqrtf(var + 1e-5f);

    const float4 gv = ((const float4*)g)[t];
    const float4 bv = ((const float4*)b)[t];
    float4 o4;
    o4.x = (v.x - mu) * rstd * gv.x + bv.x;
    o4.y = (v.y - mu) * rstd * gv.y + bv.y;
    o4.z = (v.z - mu) * rstd * gv.z + bv.z;
    o4.w = (v.w - mu) * rstd * gv.w + bv.w;
    ((float4*)(out + (size_t)row * DIM))[t] = o4;
}

// ---------------------------------------------------------------------------
// SGEMM: C[M,N] = A[M,K] @ W[K,N] + bias (+res) (+gelu)
// 128x128x8 tiles, 256 threads, 8x8 microtile via packed f32x2 (FFMA2).
// EPI: 0 = bias, 1 = bias + residual, 2 = bias + exact GELU
// ---------------------------------------------------------------------------
template<int EPI>
__global__ __launch_bounds__(256, 2) void gemm_kernel(
    const float* __restrict__ A, const float* __restrict__ W,
    const float* __restrict__ bias, const float* __restrict__ res,
    float* __restrict__ C, int M, int N, int K)
{
    __shared__ float As[2][8][132];   // transposed A tile, padded (row = 528B, 16B aligned)
    __shared__ float Ws[2][8][128];

    const int tid = threadIdx.x;
    const int tx = tid & 15;          // 0..15 -> N microtile
    const int ty = tid >> 4;          // 0..15 -> M microtile
    const int ar = tid >> 1, ac = (tid & 1) * 4;   // A tile load coords
    const int wr = tid >> 5, wc = (tid & 31) * 4;  // W tile load coords

    const float* Aptr = A + (size_t)(blockIdx.y * 128 + ar) * K + ac;
    const float* Wptr = W + (size_t)wr * N + blockIdx.x * 128 + wc;

    // stage 0
    float4 av = *(const float4*)Aptr;
    float4 wv = *(const float4*)Wptr;
    As[0][ac + 0][ar] = av.x; As[0][ac + 1][ar] = av.y;
    As[0][ac + 2][ar] = av.z; As[0][ac + 3][ar] = av.w;
    *(float4*)&Ws[0][wr][wc] = wv;
    __syncthreads();

    u64 acc2[8][4] = {};              // [mi][nj-pair] packed f32x2 accumulators
    const int nk = K >> 3;
    for (int kt = 0; kt < nk; kt++) {
        const int buf = kt & 1;
        if (kt + 1 < nk) {  // prefetch next tile from gmem
            av = *(const float4*)(Aptr + (kt + 1) * 8);
            wv = *(const float4*)(Wptr + (size_t)(kt + 1) * 8 * N);
        }
        #pragma unroll
        for (int kk = 0; kk < 8; kk++) {
            const float4 a0 = *(const float4*)&As[buf][kk][ty * 8];
            const float4 a1 = *(const float4*)&As[buf][kk][ty * 8 + 4];
            const ulonglong2 w0 = *(const ulonglong2*)&Ws[buf][kk][tx * 8];
            const ulonglong2 w1 = *(const ulonglong2*)&Ws[buf][kk][tx * 8 + 4];
            const u64 bp[4] = { w0.x, w0.y, w1.x, w1.y };
            const float a[8] = { a0.x, a0.y, a0.z, a0.w, a1.x, a1.y, a1.z, a1.w };
            #pragma unroll
            for (int i = 0; i < 8; i++) {
                const u64 as_ = splat2(a[i]);
                #pragma unroll
                for (int j = 0; j < 4; j++)
                    acc2[i][j] = ffma2(as_, bp[j], acc2[i][j]);
            }
        }
        if (kt + 1 < nk) {
            const int nb = buf ^ 1;
            As[nb][ac + 0][ar] = av.x; As[nb][ac + 1][ar] = av.y;
            As[nb][ac + 2][ar] = av.z; As[nb][ac + 3][ar] = av.w;
            *(float4*)&Ws[nb][wr][wc] = wv;
            __syncthreads();
        }
    }

    // epilogue
    const int row0 = blockIdx.y * 128 + ty * 8;
    const int col  = blockIdx.x * 128 + tx * 8;
    float br[8];
    *(float4*)&br[0] = *(const float4*)&bias[col];
    *(float4*)&br[4] = *(const float4*)&bias[col + 4];
    #pragma unroll
    for (int i = 0; i < 8; i++) {
        const size_t off = (size_t)(row0 + i) * N + col;
        float t[8];
        #pragma unroll
        for (int j = 0; j < 4; j++) unpk2(acc2[i][j], t[2*j], t[2*j+1]);
        #pragma unroll
        for (int j = 0; j < 8; j++) t[j] += br[j];
        if (EPI == 1) {
            const float4 r0 = *(const float4*)(res + off);
            const float4 r1 = *(const float4*)(res + off + 4);
            t[0] += r0.x; t[1] += r0.y; t[2] += r0.z; t[3] += r0.w;
            t[4] += r1.x; t[5] += r1.y; t[6] += r1.z; t[7] += r1.w;
        }
        if (EPI == 2) {
            #pragma unroll
            for (int j = 0; j < 8; j++) t[j] = t[j] * normcdff(t[j]);  // exact GELU
        }
        *(float4*)(C + off)     = make_float4(t[0], t[1], t[2], t[3]);
        *(float4*)(C + off + 4) = make_float4(t[4], t[5], t[6], t[7]);
    }
}

// ---------------------------------------------------------------------------
// Attention: grid = (SEQ/128, B*NH). Block = 128 threads; one q-row per
// thread, K/V staged in smem in 64-row tiles, online softmax with
// rare-rescale. All math packed f32x2; QK dot uses 4 independent chains.
// ---------------------------------------------------------------------------
__global__ __launch_bounds__(128) void attn_kernel(
    const float* __restrict__ q, const float* __restrict__ k,
    const float* __restrict__ v, float* __restrict__ outp)
{
    __shared__ float Ks[64][68];   // row = 272B (16B aligned)
    __shared__ float Vs[64][68];

    const int bh = blockIdx.y;
    const int b = bh >> 4, h = bh & 15;
    const int qrow = blockIdx.x * 128 + threadIdx.x;
    const size_t qoff  = ((size_t)(b * SEQ + qrow)) * DIM + h * HD;
    const size_t kbase = ((size_t)(b * SEQ)) * DIM + h * HD;

    u64 qp[32];                       // 64 q values as 32 packed pairs
    #pragma unroll
    for (int i = 0; i < 16; i++) {
        const ulonglong2 t = *(const ulonglong2*)(q + qoff + i * 4);
        qp[2*i] = t.x; qp[2*i+1] = t.y;
    }
    u64 o2[32] = {};                  // packed output accumulators
    float m = -1e30f, l = 0.f;

    for (int kt = 0; kt < SEQ / 64; kt++) {
        __syncthreads();   // previous tile fully consumed before overwrite
        #pragma unroll
        for (int it = 0; it < 8; it++) {
            const int idx = it * 128 + threadIdx.x;    // 0..1023
            const int r = idx >> 4, c4 = (idx & 15) * 4;
            const size_t gp = kbase + (size_t)(kt * 64 + r) * DIM + c4;
            *(float4*)&Ks[r][c4] = *(const float4*)(k + gp);
            *(float4*)&Vs[r][c4] = *(const float4*)(v + gp);
        }
        __syncthreads();

        #pragma unroll 2
        for (int j = 0; j < 64; j++) {
            // QK dot: 4 independent packed chains
            u64 s0 = 0, s1 = 0, s2 = 0, s3 = 0;
            #pragma unroll
            for (int d4 = 0; d4 < 16; d4 += 2) {
                const ulonglong2 k0 = *(const ulonglong2*)&Ks[j][d4 * 4];
                const ulonglong2 k1 = *(const ulonglong2*)&Ks[j][d4 * 4 + 4];
                s0 = ffma2(qp[2*d4],   k0.x, s0);
                s1 = ffma2(qp[2*d4+1], k0.y, s1);
                s2 = ffma2(qp[2*d4+2], k1.x, s2);
                s3 = ffma2(qp[2*d4+3], k1.y, s3);
            }
            float slo, shi;
            unpk2(fadd2(fadd2(s0, s1), fadd2(s2, s3)), slo, shi);
            const float s = (slo + shi) * 0.125f;   // 1/sqrt(64)

            float p;
            if (s > m) {
                const float corr = __expf(m - s);
                m = s;
                l *= corr;
                const u64 c2 = splat2(corr);
                #pragma unroll
                for (int d = 0; d < 32; d++) o2[d] = fmul2(o2[d], c2);
                p = 1.f;
            } else {
                p = __expf(s - m);
            }
            l += p;
            const u64 p2 = splat2(p);
            #pragma unroll
            for (int d4 = 0; d4 < 16; d4 += 2) {
                const ulonglong2 v0 = *(const ulonglong2*)&Vs[j][d4 * 4];
                const ulonglong2 v1 = *(const ulonglong2*)&Vs[j][d4 * 4 + 4];
                o2[2*d4]   = ffma2(p2, v0.x, o2[2*d4]);
                o2[2*d4+1] = ffma2(p2, v0.y, o2[2*d4+1]);
                o2[2*d4+2] = ffma2(p2, v1.x, o2[2*d4+2]);
                o2[2*d4+3] = ffma2(p2, v1.y, o2[2*d4+3]);
            }
        }
    }

    const u64 inv2 = splat2(1.f / l);
    #pragma unroll
    for (int i = 0; i < 16; i++) {
        ulonglong2 t;
        t.x = fmul2(o2[2*i],   inv2);
        t.y = fmul2(o2[2*i+1], inv2);
        *(ulonglong2*)(outp + qoff + i * 4) = t;
    }
}

// ---------------------------------------------------------------------------
// Launch (graph-capturable: kernel launches only)
// ---------------------------------------------------------------------------
extern "C" void kernel_launch(void* const* d_in, const int* in_sizes, int n_in,
                              void* d_out, int out_size)
{
    const float* x     = (const float*)d_in[0];
    const float* ln1_g = (const float*)d_in[1];
    const float* ln1_b = (const float*)d_in[2];
    const float* wq = (const float*)d_in[3];
    const float* bq = (const float*)d_in[4];
    const float* wk = (const float*)d_in[5];
    const float* bk = (const float*)d_in[6];
    const float* wv = (const float*)d_in[7];
    const float* bv = (const float*)d_in[8];
    const float* wo = (const float*)d_in[9];
    const float* bo = (const float*)d_in[10];
    const float* w1 = (const float*)d_in[11];
    const float* b1 = (const float*)d_in[12];
    const float* w2 = (const float*)d_in[13];
    const float* b2 = (const float*)d_in[14];
    const float* ln2_g = (const float*)d_in[15];
    const float* ln2_b = (const float*)d_in[16];
    float* out = (float*)d_out;

    float *h, *q, *k, *v, *attn, *x1, *h2, *ff;
    cudaGetSymbolAddress((void**)&h,    g_h);
    cudaGetSymbolAddress((void**)&q,    g_q);
    cudaGetSymbolAddress((void**)&k,    g_k);
    cudaGetSymbolAddress((void**)&v,    g_v);
    cudaGetSymbolAddress((void**)&attn, g_attn);
    cudaGetSymbolAddress((void**)&x1,   g_x1);
    cudaGetSymbolAddress((void**)&h2,   g_h2);
    cudaGetSymbolAddress((void**)&ff,   g_ff);

    const dim3 gD(DIM / 128, TOK / 128);   // (8, 32)
    const dim3 gF(DFF / 128, TOK / 128);   // (32, 32)

    ln_kernel<<<TOK, 256>>>(x, ln1_g, ln1_b, h);
    gemm_kernel<0><<<gD, 256>>>(h, wq, bq, nullptr, q, TOK, DIM, DIM);
    gemm_kernel<0><<<gD, 256>>>(h, wk, bk, nullptr, k, TOK, DIM, DIM);
    gemm_kernel<0><<<gD, 256>>>(h, wv, bv, nullptr, v, TOK, DIM, DIM);
    attn_kernel<<<dim3(SEQ / 128, BATCH * NH), 128>>>(q, k, v, attn);
    gemm_kernel<1><<<gD, 256>>>(attn, wo, bo, x, x1, TOK, DIM, DIM);
    ln_kernel<<<TOK, 256>>>(x1, ln2_g, ln2_b, h2);
    gemm_kernel<2><<<gF, 256>>>(h2, w1, b1, nullptr, ff, TOK, DFF, DIM);
    gemm_kernel<1><<<gD, 256>>>(ff, w2, b2, x1, out, TOK, DIM, DFF);
}

// round 7
// speedup vs baseline: 1.4442x; 1.4442x over previous
#include <cuda_runtime.h>
#include <cuda_bf16.h>
#include <math.h>
#include <cstdint>

// ---------------------------------------------------------------------------
// Encoder_84413287236054 : fp32 transformer encoder layer on GB300
// Round 4: GEMMs on tensor pipe via mma.sync bf16 (hi/lo split, fp32 acc).
// (tcgen05 PTX is rejected: harness compiles at .target sm_103 baseline.)
// ---------------------------------------------------------------------------

#define TOK  4096
#define DIM  1024
#define DFF  4096
#define NH   16
#define HD   64
#define SEQ  2048
#define BATCH 2

typedef unsigned long long u64;
typedef __nv_bfloat16 bf16;

// ---- packed f32x2 helpers (attention) --------------------------------------
__device__ __forceinline__ u64 splat2(float x) { u64 r; asm("mov.b64 %0,{%1,%1};" : "=l"(r) : "f"(x)); return r; }
__device__ __forceinline__ void unpk2(u64 v, float& a, float& b) { asm("mov.b64 {%0,%1},%2;" : "=f"(a), "=f"(b) : "l"(v)); }
__device__ __forceinline__ u64 ffma2(u64 a, u64 b, u64 c) { u64 d; asm("fma.rn.f32x2 %0,%1,%2,%3;" : "=l"(d) : "l"(a), "l"(b), "l"(c)); return d; }
__device__ __forceinline__ u64 fmul2(u64 a, u64 b) { u64 d; asm("mul.rn.f32x2 %0,%1,%2;" : "=l"(d) : "l"(a), "l"(b)); return d; }
__device__ __forceinline__ u64 fadd2(u64 a, u64 b) { u64 d; asm("add.rn.f32x2 %0,%1,%2;" : "=l"(d) : "l"(a), "l"(b)); return d; }

// ---- tensor-core primitives (compute_103-legal) ----------------------------
__device__ __forceinline__ uint32_t smem_u32(const void* p) {
    uint32_t a;
    asm("{ .reg .u64 t; cvta.to.shared.u64 t, %1; cvt.u32.u64 %0, t; }" : "=r"(a) : "l"(p));
    return a;
}
__device__ __forceinline__ void ldmx4(uint32_t* r, uint32_t addr) {
    asm volatile("ldmatrix.sync.aligned.m8n8.x4.shared.b16 {%0,%1,%2,%3},[%4];"
        : "=r"(r[0]), "=r"(r[1]), "=r"(r[2]), "=r"(r[3]) : "r"(addr));
}
__device__ __forceinline__ void mma_bf16(float* c, const uint32_t* a, const uint32_t* b) {
    asm volatile("mma.sync.aligned.m16n8k16.row.col.f32.bf16.bf16.f32 "
        "{%0,%1,%2,%3},{%4,%5,%6,%7},{%8,%9},{%0,%1,%2,%3};"
        : "+f"(c[0]), "+f"(c[1]), "+f"(c[2]), "+f"(c[3])
        : "r"(a[0]), "r"(a[1]), "r"(a[2]), "r"(a[3]), "r"(b[0]), "r"(b[1]));
}

// ---------------- scratch (allocation-free) ---------------------------------
__device__ bf16  g_hh [TOK * DIM], g_hl [TOK * DIM];     // LN1 out hi/lo
__device__ float g_q  [TOK * DIM], g_k [TOK * DIM], g_v [TOK * DIM];
__device__ bf16  g_ath[TOK * DIM], g_atl[TOK * DIM];     // attn out hi/lo
__device__ float g_x1 [TOK * DIM];
__device__ bf16  g_h2h[TOK * DIM], g_h2l[TOK * DIM];     // LN2 out hi/lo
__device__ bf16  g_ffh[TOK * DFF], g_ffl[TOK * DFF];     // GELU out hi/lo
// transposed+split weights: [N, K]
__device__ bf16 g_wqh[DIM * DIM], g_wql[DIM * DIM];
__device__ bf16 g_wkh[DIM * DIM], g_wkl[DIM * DIM];
__device__ bf16 g_wvh[DIM * DIM], g_wvl[DIM * DIM];
__device__ bf16 g_woh[DIM * DIM], g_wol[DIM * DIM];
__device__ bf16 g_w1h[DFF * DIM], g_w1l[DFF * DIM];
__device__ bf16 g_w2h[DIM * DFF], g_w2l[DIM * DFF];

__device__ __forceinline__ void split1(float x, bf16& h, bf16& l) {
    h = __float2bfloat16(x);
    l = __float2bfloat16(x - __bfloat162float(h));
}

// ---------------------------------------------------------------------------
// Weight transpose + hi/lo split: W[K,N] fp32 -> Th,Tl [N,K] bf16
// ---------------------------------------------------------------------------
__global__ __launch_bounds__(256) void wsplit(
    const float* __restrict__ W, bf16* __restrict__ Th, bf16* __restrict__ Tl,
    int K, int N)
{
    __shared__ float t[32][33];
    const int n0 = blockIdx.x * 32, k0 = blockIdx.y * 32;
    const int tx = threadIdx.x & 31, ty = threadIdx.x >> 5;   // 32 x 8
    #pragma unroll
    for (int i = ty; i < 32; i += 8)
        t[i][tx] = W[(size_t)(k0 + i) * N + n0 + tx];
    __syncthreads();
    #pragma unroll
    for (int i = ty; i < 32; i += 8) {
        const float x = t[tx][i];            // W[k0+tx][n0+i]
        bf16 h, l; split1(x, h, l);
        Th[(size_t)(n0 + i) * K + k0 + tx] = h;
        Tl[(size_t)(n0 + i) * K + k0 + tx] = l;
    }
}

// ---------------------------------------------------------------------------
// LayerNorm -> bf16 hi/lo
// ---------------------------------------------------------------------------
__global__ __launch_bounds__(256) void ln_split(
    const float* __restrict__ x, const float* __restrict__ g,
    const float* __restrict__ b, bf16* __restrict__ oh, bf16* __restrict__ ol)
{
    const int row = blockIdx.x;
    const int t = threadIdx.x;
    const float4 v = ((const float4*)(x + (size_t)row * DIM))[t];

    float s  = v.x + v.y + v.z + v.w;
    float ss = v.x*v.x + v.y*v.y + v.z*v.z + v.w*v.w;
    #pragma unroll
    for (int o = 16; o; o >>= 1) {
        s  += __shfl_xor_sync(0xffffffffu, s,  o);
        ss += __shfl_xor_sync(0xffffffffu, ss, o);
    }
    __shared__ float sm[8], sm2[8];
    if ((t & 31) == 0) { sm[t >> 5] = s; sm2[t >> 5] = ss; }
    __syncthreads();
    float ts = 0.f, tss = 0.f;
    #pragma unroll
    for (int i = 0; i < 8; i++) { ts += sm[i]; tss += sm2[i]; }

    const float mu   = ts * (1.0f / DIM);
    const float rstd = rsqrtf(tss * (1.0f / DIM) - mu * mu + 1e-5f);
    const float4 gv = ((const float4*)g)[t];
    const float4 bv = ((const float4*)b)[t];
    float y[4];
    y[0] = (v.x - mu) * rstd * gv.x + bv.x;
    y[1] = (v.y - mu) * rstd * gv.y + bv.y;
    y[2] = (v.z - mu) * rstd * gv.z + bv.z;
    y[3] = (v.w - mu) * rstd * gv.w + bv.w;
    bf16 h[4], l[4];
    #pragma unroll
    for (int i = 0; i < 4; i++) split1(y[i], h[i], l[i]);
    __nv_bfloat162 h2[2] = { __halves2bfloat162(h[0], h[1]), __halves2bfloat162(h[2], h[3]) };
    __nv_bfloat162 l2[2] = { __halves2bfloat162(l[0], l[1]), __halves2bfloat162(l[2], l[3]) };
    *(uint2*)(oh + (size_t)row * DIM + t * 4) = *(uint2*)h2;
    *(uint2*)(ol + (size_t)row * DIM + t * 4) = *(uint2*)l2;
}

// ---------------------------------------------------------------------------
// Tensor-core GEMM: C[M,N] = (Ah+Al)[M,K] @ (Bh+Bl)^T   (B stored [N,K])
// 3 bf16 MMAs per k16 (AhBh, AhBl, AlBh), fp32 accumulators.
// Block 256 thr = 8 warps; CTA tile 128x128; warp tile 64x32; K-chunk 32,
// double-buffered smem (80B row pitch -> ldmatrix conflict-free).
// EPI: 0 = +bias -> fp32 C; 1 = +bias+res -> fp32 C; 2 = +bias, GELU -> bf16 hi/lo
// ---------------------------------------------------------------------------
#define ARR_B  10240u                   // 128 rows * 80 bytes
#define BUFSZ  40960u                   // 4 arrays (Ah, Al, Bh, Bl)
#define MM_SMEM (2u * BUFSZ)            // 80 KB

template<int EPI>
__global__ __launch_bounds__(256, 1) void mm_tc(
    const bf16* __restrict__ Ah, const bf16* __restrict__ Al,
    const bf16* __restrict__ Bh, const bf16* __restrict__ Bl,
    const float* __restrict__ bias, const float* __restrict__ res,
    float* __restrict__ C, bf16* __restrict__ Ch, bf16* __restrict__ Cl,
    int M, int N, int K)
{
    extern __shared__ char smem[];
    const uint32_t sb = smem_u32(smem);
    const int tid = threadIdx.x, wid = tid >> 5, lid = tid & 31;
    const int wm = wid & 1, wn = wid >> 1;            // 2 x 4 warp grid
    const int m0 = blockIdx.y * 128, n0 = blockIdx.x * 128;

    // per-thread gmem load coords (2 x 16B units per array)
    const int r0_ = tid >> 2, c0_ = tid & 3;          // unit 0: rows 0..63
    const int r1_ = r0_ + 64;                         // unit 1: rows 64..127

    const bf16* srcs[4] = { Ah, Al, Bh, Bl };
    const int   base4[4] = { m0, m0, n0, n0 };

    auto fetch = [&](int kt, uint4* pf) {
        #pragma unroll
        for (int a = 0; a < 4; a++) {
            const bf16* s = srcs[a] + (size_t)base4[a] * K + kt * 32;
            pf[a * 2 + 0] = *(const uint4*)(s + (size_t)r0_ * K + c0_ * 8);
            pf[a * 2 + 1] = *(const uint4*)(s + (size_t)r1_ * K + c0_ * 8);
        }
    };
    auto commit = [&](int buf, const uint4* pf) {
        char* bb = smem + buf * BUFSZ;
        #pragma unroll
        for (int a = 0; a < 4; a++) {
            *(uint4*)(bb + a * ARR_B + r0_ * 80 + c0_ * 16) = pf[a * 2 + 0];
            *(uint4*)(bb + a * ARR_B + r1_ * 80 + c0_ * 16) = pf[a * 2 + 1];
        }
    };

    float acc[4][4][4] = {};

    // ldmatrix per-lane base offsets
    const int arow = wm * 64 + (lid & 7) + ((lid >> 3) & 1) * 8;
    const uint32_t acolb = ((lid >> 4) & 1) * 16;
    const int brow = wn * 32 + (lid & 7) + ((lid >> 4) & 1) * 8;
    const uint32_t bcolb = ((lid >> 3) & 1) * 16;

    {
        uint4 pf[8];
        fetch(0, pf);
        commit(0, pf);
    }
    __syncthreads();

    const int nk = K >> 5;
    for (int kt = 0; kt < nk; kt++) {
        const int buf = kt & 1;
        uint4 pf[8];
        if (kt + 1 < nk) fetch(kt + 1, pf);

        const uint32_t bb = sb + buf * BUFSZ;
        #pragma unroll
        for (int kh = 0; kh < 2; kh++) {
            uint32_t ah[4][4], al[4][4], bh[4][2], bl[4][2];
            #pragma unroll
            for (int mf = 0; mf < 4; mf++) {
                const uint32_t ad = bb + (arow + mf * 16) * 80 + acolb + kh * 32;
                ldmx4(ah[mf], ad);
                ldmx4(al[mf], ad + ARR_B);
            }
            #pragma unroll
            for (int g2 = 0; g2 < 2; g2++) {
                const uint32_t bd = bb + 2 * ARR_B + (brow + g2 * 16) * 80 + bcolb + kh * 32;
                uint32_t t[4];
                ldmx4(t, bd);
                bh[g2*2][0] = t[0]; bh[g2*2][1] = t[1];
                bh[g2*2+1][0] = t[2]; bh[g2*2+1][1] = t[3];
                ldmx4(t, bd + ARR_B);
                bl[g2*2][0] = t[0]; bl[g2*2][1] = t[1];
                bl[g2*2+1][0] = t[2]; bl[g2*2+1][1] = t[3];
            }
            #pragma unroll
            for (int mf = 0; mf < 4; mf++)
                #pragma unroll
                for (int nf = 0; nf < 4; nf++) {
                    mma_bf16(acc[mf][nf], ah[mf], bh[nf]);
                    mma_bf16(acc[mf][nf], ah[mf], bl[nf]);
                    mma_bf16(acc[mf][nf], al[mf], bh[nf]);
                }
        }

        if (kt + 1 < nk) {
            commit(buf ^ 1, pf);
            __syncthreads();
        }
    }

    // ---------------- epilogue ----------------
    #pragma unroll
    for (int mf = 0; mf < 4; mf++) {
        const int rowA = m0 + wm * 64 + mf * 16 + (lid >> 2);
        const int rowB = rowA + 8;
        #pragma unroll
        for (int nf = 0; nf < 4; nf++) {
            const int col = n0 + wn * 32 + nf * 8 + (lid & 3) * 2;
            const float2 b2 = *(const float2*)(bias + col);
            float v0 = acc[mf][nf][0] + b2.x;
            float v1 = acc[mf][nf][1] + b2.y;
            float v2 = acc[mf][nf][2] + b2.x;
            float v3 = acc[mf][nf][3] + b2.y;
            const size_t offA = (size_t)rowA * N + col;
            const size_t offB = (size_t)rowB * N + col;
            if (EPI == 1) {
                const float2 rA = *(const float2*)(res + offA);
                const float2 rB = *(const float2*)(res + offB);
                v0 += rA.x; v1 += rA.y; v2 += rB.x; v3 += rB.y;
            }
            if (EPI == 2) {
                v0 = v0 * normcdff(v0); v1 = v1 * normcdff(v1);
                v2 = v2 * normcdff(v2); v3 = v3 * normcdff(v3);
                bf16 h0, l0, h1, l1;
                split1(v0, h0, l0); split1(v1, h1, l1);
                __nv_bfloat162 hA = __halves2bfloat162(h0, h1);
                __nv_bfloat162 lA = __halves2bfloat162(l0, l1);
                split1(v2, h0, l0); split1(v3, h1, l1);
                __nv_bfloat162 hB = __halves2bfloat162(h0, h1);
                __nv_bfloat162 lB = __halves2bfloat162(l0, l1);
                *(uint32_t*)(Ch + offA) = *(uint32_t*)&hA;
                *(uint32_t*)(Cl + offA) = *(uint32_t*)&lA;
                *(uint32_t*)(Ch + offB) = *(uint32_t*)&hB;
                *(uint32_t*)(Cl + offB) = *(uint32_t*)&lB;
            } else {
                *(float2*)(C + offA) = make_float2(v0, v1);
                *(float2*)(C + offB) = make_float2(v2, v3);
            }
        }
    }
}

// ---------------------------------------------------------------------------
// Attention (SIMT fp32, packed f32x2), epilogue writes bf16 hi/lo
// ---------------------------------------------------------------------------
__global__ __launch_bounds__(128) void attn_kernel(
    const float* __restrict__ q, const float* __restrict__ k,
    const float* __restrict__ v, bf16* __restrict__ oh, bf16* __restrict__ ol)
{
    __shared__ float Ks[64][68];
    __shared__ float Vs[64][68];

    const int bh = blockIdx.y;
    const int b = bh >> 4, h = bh & 15;
    const int qrow = blockIdx.x * 128 + threadIdx.x;
    const size_t qoff  = ((size_t)(b * SEQ + qrow)) * DIM + h * HD;
    const size_t kbase = ((size_t)(b * SEQ)) * DIM + h * HD;

    u64 qp[32];
    #pragma unroll
    for (int i = 0; i < 16; i++) {
        const ulonglong2 t = *(const ulonglong2*)(q + qoff + i * 4);
        qp[2*i] = t.x; qp[2*i+1] = t.y;
    }
    u64 o2[32] = {};
    float m = -1e30f, l = 0.f;

    for (int kt = 0; kt < SEQ / 64; kt++) {
        __syncthreads();
        #pragma unroll
        for (int it = 0; it < 8; it++) {
            const int idx = it * 128 + threadIdx.x;
            const int r = idx >> 4, c4 = (idx & 15) * 4;
            const size_t gp = kbase + (size_t)(kt * 64 + r) * DIM + c4;
            *(float4*)&Ks[r][c4] = *(const float4*)(k + gp);
            *(float4*)&Vs[r][c4] = *(const float4*)(v + gp);
        }
        __syncthreads();

        #pragma unroll 2
        for (int j = 0; j < 64; j++) {
            u64 s0 = 0, s1 = 0, s2 = 0, s3 = 0;
            #pragma unroll
            for (int d4 = 0; d4 < 16; d4 += 2) {
                const ulonglong2 k0 = *(const ulonglong2*)&Ks[j][d4 * 4];
                const ulonglong2 k1 = *(const ulonglong2*)&Ks[j][d4 * 4 + 4];
                s0 = ffma2(qp[2*d4],   k0.x, s0);
                s1 = ffma2(qp[2*d4+1], k0.y, s1);
                s2 = ffma2(qp[2*d4+2], k1.x, s2);
                s3 = ffma2(qp[2*d4+3], k1.y, s3);
            }
            float slo, shi;
            unpk2(fadd2(fadd2(s0, s1), fadd2(s2, s3)), slo, shi);
            const float s = (slo + shi) * 0.125f;

            float p;
            if (s > m) {
                const float corr = __expf(m - s);
                m = s; l *= corr;
                const u64 c2 = splat2(corr);
                #pragma unroll
                for (int d = 0; d < 32; d++) o2[d] = fmul2(o2[d], c2);
                p = 1.f;
            } else {
                p = __expf(s - m);
            }
            l += p;
            const u64 p2 = splat2(p);
            #pragma unroll
            for (int d4 = 0; d4 < 16; d4 += 2) {
                const ulonglong2 v0 = *(const ulonglong2*)&Vs[j][d4 * 4];
                const ulonglong2 v1 = *(const ulonglong2*)&Vs[j][d4 * 4 + 4];
                o2[2*d4]   = ffma2(p2, v0.x, o2[2*d4]);
                o2[2*d4+1] = ffma2(p2, v0.y, o2[2*d4+1]);
                o2[2*d4+2] = ffma2(p2, v1.x, o2[2*d4+2]);
                o2[2*d4+3] = ffma2(p2, v1.y, o2[2*d4+3]);
            }
        }
    }

    const float inv = 1.f / l;
    #pragma unroll
    for (int i = 0; i < 8; i++) {
        __nv_bfloat162 hh[4], ll[4];
        #pragma unroll
        for (int j = 0; j < 4; j++) {
            float a, bq_;
            unpk2(o2[4*i + j], a, bq_);
            a *= inv; bq_ *= inv;
            bf16 h0, l0, h1, l1;
            split1(a, h0, l0); split1(bq_, h1, l1);
            hh[j] = __halves2bfloat162(h0, h1);
            ll[j] = __halves2bfloat162(l0, l1);
        }
        *(uint4*)(oh + qoff + i * 8) = *(uint4*)hh;
        *(uint4*)(ol + qoff + i * 8) = *(uint4*)ll;
    }
}

// ---------------------------------------------------------------------------
extern "C" void kernel_launch(void* const* d_in, const int* in_sizes, int n_in,
                              void* d_out, int out_size)
{
    const float* x     = (const float*)d_in[0];
    const float* ln1_g = (const float*)d_in[1];
    const float* ln1_b = (const float*)d_in[2];
    const float* wq = (const float*)d_in[3];
    const float* bq = (const float*)d_in[4];
    const float* wk = (const float*)d_in[5];
    const float* bk = (const float*)d_in[6];
    const float* wv = (const float*)d_in[7];
    const float* bv = (const float*)d_in[8];
    const float* wo = (const float*)d_in[9];
    const float* bo = (const float*)d_in[10];
    const float* w1 = (const float*)d_in[11];
    const float* b1 = (const float*)d_in[12];
    const float* w2 = (const float*)d_in[13];
    const float* b2 = (const float*)d_in[14];
    const float* ln2_g = (const float*)d_in[15];
    const float* ln2_b = (const float*)d_in[16];
    float* out = (float*)d_out;

    bf16 *hh, *hl, *ath, *atl, *h2h, *h2l, *ffh, *ffl;
    bf16 *wqh, *wql, *wkh, *wkl, *wvh, *wvl, *woh, *wol, *w1h, *w1l, *w2h, *w2l;
    float *qf, *kf, *vf, *x1;
    cudaGetSymbolAddress((void**)&hh,  g_hh);  cudaGetSymbolAddress((void**)&hl,  g_hl);
    cudaGetSymbolAddress((void**)&qf,  g_q);   cudaGetSymbolAddress((void**)&kf,  g_k);
    cudaGetSymbolAddress((void**)&vf,  g_v);
    cudaGetSymbolAddress((void**)&ath, g_ath); cudaGetSymbolAddress((void**)&atl, g_atl);
    cudaGetSymbolAddress((void**)&x1,  g_x1);
    cudaGetSymbolAddress((void**)&h2h, g_h2h); cudaGetSymbolAddress((void**)&h2l, g_h2l);
    cudaGetSymbolAddress((void**)&ffh, g_ffh); cudaGetSymbolAddress((void**)&ffl, g_ffl);
    cudaGetSymbolAddress((void**)&wqh, g_wqh); cudaGetSymbolAddress((void**)&wql, g_wql);
    cudaGetSymbolAddress((void**)&wkh, g_wkh); cudaGetSymbolAddress((void**)&wkl, g_wkl);
    cudaGetSymbolAddress((void**)&wvh, g_wvh); cudaGetSymbolAddress((void**)&wvl, g_wvl);
    cudaGetSymbolAddress((void**)&woh, g_woh); cudaGetSymbolAddress((void**)&wol, g_wol);
    cudaGetSymbolAddress((void**)&w1h, g_w1h); cudaGetSymbolAddress((void**)&w1l, g_w1l);
    cudaGetSymbolAddress((void**)&w2h, g_w2h); cudaGetSymbolAddress((void**)&w2l, g_w2l);

    cudaFuncSetAttribute(mm_tc<0>, cudaFuncAttributeMaxDynamicSharedMemorySize, MM_SMEM);
    cudaFuncSetAttribute(mm_tc<1>, cudaFuncAttributeMaxDynamicSharedMemorySize, MM_SMEM);
    cudaFuncSetAttribute(mm_tc<2>, cudaFuncAttributeMaxDynamicSharedMemorySize, MM_SMEM);

    // weight transpose + split
    wsplit<<<dim3(DIM/32, DIM/32), 256>>>(wq, wqh, wql, DIM, DIM);
    wsplit<<<dim3(DIM/32, DIM/32), 256>>>(wk, wkh, wkl, DIM, DIM);
    wsplit<<<dim3(DIM/32, DIM/32), 256>>>(wv, wvh, wvl, DIM, DIM);
    wsplit<<<dim3(DIM/32, DIM/32), 256>>>(wo, woh, wol, DIM, DIM);
    wsplit<<<dim3(DFF/32, DIM/32), 256>>>(w1, w1h, w1l, DIM, DFF);
    wsplit<<<dim3(DIM/32, DFF/32), 256>>>(w2, w2h, w2l, DFF, DIM);

    const dim3 gD(DIM / 128, TOK / 128);   // (8, 32)
    const dim3 gF(DFF / 128, TOK / 128);   // (32, 32)

    ln_split<<<TOK, 256>>>(x, ln1_g, ln1_b, hh, hl);
    mm_tc<0><<<gD, 256, MM_SMEM>>>(hh, hl, wqh, wql, bq, nullptr, qf, nullptr, nullptr, TOK, DIM, DIM);
    mm_tc<0><<<gD, 256, MM_SMEM>>>(hh, hl, wkh, wkl, bk, nullptr, kf, nullptr, nullptr, TOK, DIM, DIM);
    mm_tc<0><<<gD, 256, MM_SMEM>>>(hh, hl, wvh, wvl, bv, nullptr, vf, nullptr, nullptr, TOK, DIM, DIM);
    attn_kernel<<<dim3(SEQ / 128, BATCH * NH), 128>>>(qf, kf, vf, ath, atl);
    mm_tc<1><<<gD, 256, MM_SMEM>>>(ath, atl, woh, wol, bo, x, x1, nullptr, nullptr, TOK, DIM, DIM);
    ln_split<<<TOK, 256>>>(x1, ln2_g, ln2_b, h2h, h2l);
    mm_tc<2><<<gF, 256, MM_SMEM>>>(h2h, h2l, w1h, w1l, b1, nullptr, nullptr, ffh, ffl, TOK, DFF, DIM);
    mm_tc<1><<<gD, 256, MM_SMEM>>>(ffh, ffl, w2h, w2l, b2, x1, out, nullptr, nullptr, TOK, DIM, DFF);
}

// round 9
// speedup vs baseline: 2.5648x; 1.7759x over previous
#include <cuda_runtime.h>
#include <cuda_bf16.h>
#include <math.h>
#include <cstdint>

// ---------------------------------------------------------------------------
// Encoder_84413287236054 : fp32 transformer encoder layer on GB300
// Round 8: GEMMs + flash attention all on tensor pipe (mma.sync bf16 hi/lo).
// ---------------------------------------------------------------------------

#define TOK  4096
#define DIM  1024
#define DFF  4096
#define NH   16
#define HD   64
#define SEQ  2048
#define BATCH 2

typedef unsigned long long u64;
typedef __nv_bfloat16 bf16;

// ---- tensor-core primitives (compute_103-legal) ----------------------------
__device__ __forceinline__ uint32_t smem_u32(const void* p) {
    uint32_t a;
    asm("{ .reg .u64 t; cvta.to.shared.u64 t, %1; cvt.u32.u64 %0, t; }" : "=r"(a) : "l"(p));
    return a;
}
__device__ __forceinline__ void ldmx4(uint32_t* r, uint32_t addr) {
    asm volatile("ldmatrix.sync.aligned.m8n8.x4.shared.b16 {%0,%1,%2,%3},[%4];"
        : "=r"(r[0]), "=r"(r[1]), "=r"(r[2]), "=r"(r[3]) : "r"(addr));
}
__device__ __forceinline__ void mma_bf16(float* c, const uint32_t* a, const uint32_t* b) {
    asm volatile("mma.sync.aligned.m16n8k16.row.col.f32.bf16.bf16.f32 "
        "{%0,%1,%2,%3},{%4,%5,%6,%7},{%8,%9},{%0,%1,%2,%3};"
        : "+f"(c[0]), "+f"(c[1]), "+f"(c[2]), "+f"(c[3])
        : "r"(a[0]), "r"(a[1]), "r"(a[2]), "r"(a[3]), "r"(b[0]), "r"(b[1]));
}

__device__ __forceinline__ void split1(float x, bf16& h, bf16& l) {
    h = __float2bfloat16(x);
    l = __float2bfloat16(x - __bfloat162float(h));
}
__device__ __forceinline__ uint32_t packbf2(bf16 a, bf16 b) {
    __nv_bfloat162 t = __halves2bfloat162(a, b);
    return *(uint32_t*)&t;
}
// split two floats into packed-bf16 hi word + lo word
__device__ __forceinline__ void split2pack(float a, float b, uint32_t& hp, uint32_t& lp) {
    bf16 ha, la, hb, lb;
    split1(a, ha, la); split1(b, hb, lb);
    hp = packbf2(ha, hb); lp = packbf2(la, lb);
}

// ---------------- scratch (allocation-free) ---------------------------------
__device__ bf16  g_hh [TOK * DIM], g_hl [TOK * DIM];     // LN1 out hi/lo
__device__ bf16  g_qh [TOK * DIM], g_ql [TOK * DIM];     // Q (pre-scaled) hi/lo
__device__ bf16  g_kh [TOK * DIM], g_kl [TOK * DIM];
__device__ bf16  g_vh [TOK * DIM], g_vl [TOK * DIM];
__device__ bf16  g_ath[TOK * DIM], g_atl[TOK * DIM];     // attn out hi/lo
__device__ float g_x1 [TOK * DIM];
__device__ bf16  g_h2h[TOK * DIM], g_h2l[TOK * DIM];     // LN2 out hi/lo
__device__ bf16  g_ffh[TOK * DFF], g_ffl[TOK * DFF];     // GELU out hi/lo
// transposed+split weights: [N, K]
__device__ bf16 g_wqh[DIM * DIM], g_wql[DIM * DIM];
__device__ bf16 g_wkh[DIM * DIM], g_wkl[DIM * DIM];
__device__ bf16 g_wvh[DIM * DIM], g_wvl[DIM * DIM];
__device__ bf16 g_woh[DIM * DIM], g_wol[DIM * DIM];
__device__ bf16 g_w1h[DFF * DIM], g_w1l[DFF * DIM];
__device__ bf16 g_w2h[DIM * DFF], g_w2l[DIM * DFF];

// ---------------------------------------------------------------------------
// Weight transpose + hi/lo split: W[K,N] fp32 -> Th,Tl [N,K] bf16
// ---------------------------------------------------------------------------
__global__ __launch_bounds__(256) void wsplit(
    const float* __restrict__ W, bf16* __restrict__ Th, bf16* __restrict__ Tl,
    int K, int N)
{
    __shared__ float t[32][33];
    const int n0 = blockIdx.x * 32, k0 = blockIdx.y * 32;
    const int tx = threadIdx.x & 31, ty = threadIdx.x >> 5;
    #pragma unroll
    for (int i = ty; i < 32; i += 8)
        t[i][tx] = W[(size_t)(k0 + i) * N + n0 + tx];
    __syncthreads();
    #pragma unroll
    for (int i = ty; i < 32; i += 8) {
        const float x = t[tx][i];
        bf16 h, l; split1(x, h, l);
        Th[(size_t)(n0 + i) * K + k0 + tx] = h;
        Tl[(size_t)(n0 + i) * K + k0 + tx] = l;
    }
}

// ---------------------------------------------------------------------------
// LayerNorm -> bf16 hi/lo
// ---------------------------------------------------------------------------
__global__ __launch_bounds__(256) void ln_split(
    const float* __restrict__ x, const float* __restrict__ g,
    const float* __restrict__ b, bf16* __restrict__ oh, bf16* __restrict__ ol)
{
    const int row = blockIdx.x;
    const int t = threadIdx.x;
    const float4 v = ((const float4*)(x + (size_t)row * DIM))[t];

    float s  = v.x + v.y + v.z + v.w;
    float ss = v.x*v.x + v.y*v.y + v.z*v.z + v.w*v.w;
    #pragma unroll
    for (int o = 16; o; o >>= 1) {
        s  += __shfl_xor_sync(0xffffffffu, s,  o);
        ss += __shfl_xor_sync(0xffffffffu, ss, o);
    }
    __shared__ float sm[8], sm2[8];
    if ((t & 31) == 0) { sm[t >> 5] = s; sm2[t >> 5] = ss; }
    __syncthreads();
    float ts = 0.f, tss = 0.f;
    #pragma unroll
    for (int i = 0; i < 8; i++) { ts += sm[i]; tss += sm2[i]; }

    const float mu   = ts * (1.0f / DIM);
    const float rstd = rsqrtf(tss * (1.0f / DIM) - mu * mu + 1e-5f);
    const float4 gv = ((const float4*)g)[t];
    const float4 bv = ((const float4*)b)[t];
    float y[4];
    y[0] = (v.x - mu) * rstd * gv.x + bv.x;
    y[1] = (v.y - mu) * rstd * gv.y + bv.y;
    y[2] = (v.z - mu) * rstd * gv.z + bv.z;
    y[3] = (v.w - mu) * rstd * gv.w + bv.w;
    uint32_t hp0, lp0, hp1, lp1;
    split2pack(y[0], y[1], hp0, lp0);
    split2pack(y[2], y[3], hp1, lp1);
    *(uint2*)(oh + (size_t)row * DIM + t * 4) = make_uint2(hp0, hp1);
    *(uint2*)(ol + (size_t)row * DIM + t * 4) = make_uint2(lp0, lp1);
}

// ---------------------------------------------------------------------------
// Tensor-core GEMM: C[M,N] = (Ah+Al)[M,K] @ (Bh+Bl)^T   (B stored [N,K])
// EPI: 0=+bias->fp32; 1=+bias+res->fp32; 2=+bias,GELU->bf16 h/l;
//      3=+bias, *oscale -> bf16 h/l
// ---------------------------------------------------------------------------
#define ARR_B  10240u                   // 128 rows * 80 bytes
#define BUFSZ  40960u
#define MM_SMEM (2u * BUFSZ)

template<int EPI>
__global__ __launch_bounds__(256, 1) void mm_tc(
    const bf16* __restrict__ Ah, const bf16* __restrict__ Al,
    const bf16* __restrict__ Bh, const bf16* __restrict__ Bl,
    const float* __restrict__ bias, const float* __restrict__ res,
    float* __restrict__ C, bf16* __restrict__ Ch, bf16* __restrict__ Cl,
    int M, int N, int K, float oscale)
{
    extern __shared__ char smem[];
    const uint32_t sb = smem_u32(smem);
    const int tid = threadIdx.x, wid = tid >> 5, lid = tid & 31;
    const int wm = wid & 1, wn = wid >> 1;
    const int m0 = blockIdx.y * 128, n0 = blockIdx.x * 128;

    const int r0_ = tid >> 2, c0_ = tid & 3;
    const int r1_ = r0_ + 64;

    const bf16* srcs[4] = { Ah, Al, Bh, Bl };
    const int   base4[4] = { m0, m0, n0, n0 };

    auto fetch = [&](int kt, uint4* pf) {
        #pragma unroll
        for (int a = 0; a < 4; a++) {
            const bf16* s = srcs[a] + (size_t)base4[a] * K + kt * 32;
            pf[a * 2 + 0] = *(const uint4*)(s + (size_t)r0_ * K + c0_ * 8);
            pf[a * 2 + 1] = *(const uint4*)(s + (size_t)r1_ * K + c0_ * 8);
        }
    };
    auto commit = [&](int buf, const uint4* pf) {
        char* bb = smem + buf * BUFSZ;
        #pragma unroll
        for (int a = 0; a < 4; a++) {
            *(uint4*)(bb + a * ARR_B + r0_ * 80 + c0_ * 16) = pf[a * 2 + 0];
            *(uint4*)(bb + a * ARR_B + r1_ * 80 + c0_ * 16) = pf[a * 2 + 1];
        }
    };

    float acc[4][4][4] = {};

    const int arow = wm * 64 + (lid & 7) + ((lid >> 3) & 1) * 8;
    const uint32_t acolb = ((lid >> 4) & 1) * 16;
    const int brow = wn * 32 + (lid & 7) + ((lid >> 4) & 1) * 8;
    const uint32_t bcolb = ((lid >> 3) & 1) * 16;

    {
        uint4 pf[8];
        fetch(0, pf);
        commit(0, pf);
    }
    __syncthreads();

    const int nk = K >> 5;
    for (int kt = 0; kt < nk; kt++) {
        const int buf = kt & 1;
        uint4 pf[8];
        if (kt + 1 < nk) fetch(kt + 1, pf);

        const uint32_t bb = sb + buf * BUFSZ;
        #pragma unroll
        for (int kh = 0; kh < 2; kh++) {
            uint32_t ah[4][4], al[4][4], bh[4][2], bl[4][2];
            #pragma unroll
            for (int mf = 0; mf < 4; mf++) {
                const uint32_t ad = bb + (arow + mf * 16) * 80 + acolb + kh * 32;
                ldmx4(ah[mf], ad);
                ldmx4(al[mf], ad + ARR_B);
            }
            #pragma unroll
            for (int g2 = 0; g2 < 2; g2++) {
                const uint32_t bd = bb + 2 * ARR_B + (brow + g2 * 16) * 80 + bcolb + kh * 32;
                uint32_t t[4];
                ldmx4(t, bd);
                bh[g2*2][0] = t[0]; bh[g2*2][1] = t[1];
                bh[g2*2+1][0] = t[2]; bh[g2*2+1][1] = t[3];
                ldmx4(t, bd + ARR_B);
                bl[g2*2][0] = t[0]; bl[g2*2][1] = t[1];
                bl[g2*2+1][0] = t[2]; bl[g2*2+1][1] = t[3];
            }
            #pragma unroll
            for (int mf = 0; mf < 4; mf++)
                #pragma unroll
                for (int nf = 0; nf < 4; nf++) {
                    mma_bf16(acc[mf][nf], ah[mf], bh[nf]);
                    mma_bf16(acc[mf][nf], ah[mf], bl[nf]);
                    mma_bf16(acc[mf][nf], al[mf], bh[nf]);
                }
        }

        if (kt + 1 < nk) {
            commit(buf ^ 1, pf);
            __syncthreads();
        }
    }

    // ---------------- epilogue ----------------
    #pragma unroll
    for (int mf = 0; mf < 4; mf++) {
        const int rowA = m0 + wm * 64 + mf * 16 + (lid >> 2);
        const int rowB = rowA + 8;
        #pragma unroll
        for (int nf = 0; nf < 4; nf++) {
            const int col = n0 + wn * 32 + nf * 8 + (lid & 3) * 2;
            const float2 b2 = *(const float2*)(bias + col);
            float v0 = acc[mf][nf][0] + b2.x;
            float v1 = acc[mf][nf][1] + b2.y;
            float v2 = acc[mf][nf][2] + b2.x;
            float v3 = acc[mf][nf][3] + b2.y;
            const size_t offA = (size_t)rowA * N + col;
            const size_t offB = (size_t)rowB * N + col;
            if (EPI == 1) {
                const float2 rA = *(const float2*)(res + offA);
                const float2 rB = *(const float2*)(res + offB);
                v0 += rA.x; v1 += rA.y; v2 += rB.x; v3 += rB.y;
            }
            if (EPI == 2 || EPI == 3) {
                if (EPI == 2) {
                    v0 = v0 * normcdff(v0); v1 = v1 * normcdff(v1);
                    v2 = v2 * normcdff(v2); v3 = v3 * normcdff(v3);
                } else {
                    v0 *= oscale; v1 *= oscale; v2 *= oscale; v3 *= oscale;
                }
                uint32_t hA, lA, hB, lB;
                split2pack(v0, v1, hA, lA);
                split2pack(v2, v3, hB, lB);
                *(uint32_t*)(Ch + offA) = hA;
                *(uint32_t*)(Cl + offA) = lA;
                *(uint32_t*)(Ch + offB) = hB;
                *(uint32_t*)(Cl + offB) = lB;
            } else {
                *(float2*)(C + offA) = make_float2(v0, v1);
                *(float2*)(C + offB) = make_float2(v2, v3);
            }
        }
    }
}

// ---------------------------------------------------------------------------
// Flash attention on tensor cores (bf16 hi/lo, fp32 softmax).
// Grid (SEQ/64, B*NH). Block 128 = 4 warps; warp = 16 q-rows.
// Smem (dynamic): QH QL | KH KL | VTH VTL, each 64 rows x 72 bf16 (144B pitch).
// ---------------------------------------------------------------------------
#define APITCH 72                       // bf16 elements per smem row
#define AARR   (64 * APITCH * 2)        // 9216 bytes per array
#define A_QH   0u
#define A_QL   (1u * AARR)
#define A_KH   (2u * AARR)
#define A_KL   (3u * AARR)
#define A_VTH  (4u * AARR)
#define A_VTL  (5u * AARR)
#define ASMEM  (6u * AARR)

__global__ __launch_bounds__(128, 1) void attn_tc(
    const bf16* __restrict__ qh, const bf16* __restrict__ ql,
    const bf16* __restrict__ kh, const bf16* __restrict__ kl,
    const bf16* __restrict__ vh, const bf16* __restrict__ vl,
    bf16* __restrict__ oh, bf16* __restrict__ ol)
{
    extern __shared__ char smem[];
    const uint32_t sb = smem_u32(smem);
    const int tid = threadIdx.x, wid = tid >> 5, lid = tid & 31;
    const int bh_ = blockIdx.y;
    const int b = bh_ >> 4, h = bh_ & 15;
    const int q0 = blockIdx.x * 64;
    const size_t base = (size_t)(b * SEQ) * DIM + h * HD;   // +row*DIM

    // ---- stage Q tile into smem ----
    #pragma unroll
    for (int it = 0; it < 4; it++) {
        const int idx = it * 128 + tid;
        const int r = idx >> 3, c8 = idx & 7;
        const size_t gp = base + (size_t)(q0 + r) * DIM + c8 * 8;
        *(uint4*)(smem + A_QH + r * 144 + c8 * 16) = *(const uint4*)(qh + gp);
        *(uint4*)(smem + A_QL + r * 144 + c8 * 16) = *(const uint4*)(ql + gp);
    }
    __syncthreads();

    // ---- per-warp Q A-fragments (4 k-steps over hd) ----
    uint32_t Qh_[4][4], Ql_[4][4];
    const int arow = wid * 16 + (lid & 7) + ((lid >> 3) & 1) * 8;
    const uint32_t acol = ((lid >> 4) & 1) * 16;
    #pragma unroll
    for (int ks = 0; ks < 4; ks++) {
        const uint32_t ad = sb + arow * 144 + acol + ks * 32;
        ldmx4(Qh_[ks], ad + A_QH);
        ldmx4(Ql_[ks], ad + A_QL);
    }

    float O[8][4] = {};
    float m0_ = -1e30f, m1_ = -1e30f, l0_ = 0.f, l1_ = 0.f;

    // B-fragment lane addressing (shared by K and V^T)
    const int brow = (lid & 7) + ((lid >> 4) & 1) * 8;
    const uint32_t bcol = ((lid >> 3) & 1) * 16;

    // V transpose-load coords
    const int vp = tid & 31;            // token pair index
    const int vq = tid >> 5;            // hd 16-chunk

    for (int kt = 0; kt < SEQ / 64; kt++) {
        __syncthreads();                // previous tile fully consumed

        // ---- load K tile (row-major [kv][hd]) ----
        #pragma unroll
        for (int it = 0; it < 4; it++) {
            const int idx = it * 128 + tid;
            const int r = idx >> 3, c8 = idx & 7;
            const size_t gp = base + (size_t)(kt * 64 + r) * DIM + c8 * 8;
            *(uint4*)(smem + A_KH + r * 144 + c8 * 16) = *(const uint4*)(kh + gp);
            *(uint4*)(smem + A_KL + r * 144 + c8 * 16) = *(const uint4*)(kl + gp);
        }
        // ---- load V tile transposed -> VT[hd][kv] (paired-token 4B stores) ----
        {
            const size_t g0 = base + (size_t)(kt * 64 + 2 * vp) * DIM + vq * 16;
            const size_t g1 = g0 + DIM;
            #pragma unroll
            for (int half = 0; half < 2; half++) {
                const bf16* src = half ? vl : vh;
                const uint32_t dst = (half ? A_VTL : A_VTH);
                uint4 r0a = *(const uint4*)(src + g0);
                uint4 r0b = *(const uint4*)(src + g0 + 8);
                uint4 r1a = *(const uint4*)(src + g1);
                uint4 r1b = *(const uint4*)(src + g1 + 8);
                const ushort* s0a = (const ushort*)&r0a;
                const ushort* s0b = (const ushort*)&r0b;
                const ushort* s1a = (const ushort*)&r1a;
                const ushort* s1b = (const ushort*)&r1b;
                #pragma unroll
                for (int d = 0; d < 8; d++) {
                    *(uint32_t*)(smem + dst + (vq * 16 + d) * 144 + vp * 4) =
                        (uint32_t)s0a[d] | ((uint32_t)s1a[d] << 16);
                    *(uint32_t*)(smem + dst + (vq * 16 + 8 + d) * 144 + vp * 4) =
                        (uint32_t)s0b[d] | ((uint32_t)s1b[d] << 16);
                }
            }
        }
        __syncthreads();

        // ---- scores S = Q K^T (3-MMA hi/lo) ----
        float S[8][4] = {};
        #pragma unroll
        for (int ks = 0; ks < 4; ks++) {
            #pragma unroll
            for (int g2 = 0; g2 < 4; g2++) {
                const uint32_t bd = sb + (brow + g2 * 16) * 144 + bcol + ks * 32;
                uint32_t th[4], tl[4];
                ldmx4(th, bd + A_KH);
                ldmx4(tl, bd + A_KL);
                uint32_t bh0[2] = { th[0], th[1] }, bh1[2] = { th[2], th[3] };
                uint32_t bl0[2] = { tl[0], tl[1] }, bl1[2] = { tl[2], tl[3] };
                mma_bf16(S[g2*2],   Qh_[ks], bh0);
                mma_bf16(S[g2*2],   Qh_[ks], bl0);
                mma_bf16(S[g2*2],   Ql_[ks], bh0);
                mma_bf16(S[g2*2+1], Qh_[ks], bh1);
                mma_bf16(S[g2*2+1], Qh_[ks], bl1);
                mma_bf16(S[g2*2+1], Ql_[ks], bh1);
            }
        }

        // ---- online softmax ----
        float rm0 = -1e30f, rm1 = -1e30f;
        #pragma unroll
        for (int nf = 0; nf < 8; nf++) {
            rm0 = fmaxf(rm0, fmaxf(S[nf][0], S[nf][1]));
            rm1 = fmaxf(rm1, fmaxf(S[nf][2], S[nf][3]));
        }
        rm0 = fmaxf(rm0, __shfl_xor_sync(0xffffffffu, rm0, 1));
        rm0 = fmaxf(rm0, __shfl_xor_sync(0xffffffffu, rm0, 2));
        rm1 = fmaxf(rm1, __shfl_xor_sync(0xffffffffu, rm1, 1));
        rm1 = fmaxf(rm1, __shfl_xor_sync(0xffffffffu, rm1, 2));
        const float mn0 = fmaxf(m0_, rm0), mn1 = fmaxf(m1_, rm1);
        const float c0 = __expf(m0_ - mn0), c1 = __expf(m1_ - mn1);
        m0_ = mn0; m1_ = mn1;

        float rs0 = 0.f, rs1 = 0.f;
        #pragma unroll
        for (int nf = 0; nf < 8; nf++) {
            S[nf][0] = __expf(S[nf][0] - mn0);
            S[nf][1] = __expf(S[nf][1] - mn0);
            S[nf][2] = __expf(S[nf][2] - mn1);
            S[nf][3] = __expf(S[nf][3] - mn1);
            rs0 += S[nf][0] + S[nf][1];
            rs1 += S[nf][2] + S[nf][3];
        }
        rs0 += __shfl_xor_sync(0xffffffffu, rs0, 1);
        rs0 += __shfl_xor_sync(0xffffffffu, rs0, 2);
        rs1 += __shfl_xor_sync(0xffffffffu, rs1, 1);
        rs1 += __shfl_xor_sync(0xffffffffu, rs1, 2);
        l0_ = l0_ * c0 + rs0;
        l1_ = l1_ * c1 + rs1;
        #pragma unroll
        for (int nf = 0; nf < 8; nf++) {
            O[nf][0] *= c0; O[nf][1] *= c0;
            O[nf][2] *= c1; O[nf][3] *= c1;
        }

        // ---- P fragments (hi/lo) from S ----
        uint32_t Ph[4][4], Pl[4][4];
        #pragma unroll
        for (int t = 0; t < 4; t++) {
            split2pack(S[2*t][0],   S[2*t][1],   Ph[t][0], Pl[t][0]);
            split2pack(S[2*t][2],   S[2*t][3],   Ph[t][1], Pl[t][1]);
            split2pack(S[2*t+1][0], S[2*t+1][1], Ph[t][2], Pl[t][2]);
            split2pack(S[2*t+1][2], S[2*t+1][3], Ph[t][3], Pl[t][3]);
        }

        // ---- O += P V (3-MMA hi/lo), V^T layout [hd][kv] ----
        #pragma unroll
        for (int t = 0; t < 4; t++) {          // kv k-steps
            #pragma unroll
            for (int g2 = 0; g2 < 4; g2++) {   // hd n-groups of 16
                const uint32_t bd = sb + (brow + g2 * 16) * 144 + bcol + t * 32;
                uint32_t th[4], tl[4];
                ldmx4(th, bd + A_VTH);
                ldmx4(tl, bd + A_VTL);
                uint32_t bh0[2] = { th[0], th[1] }, bh1[2] = { th[2], th[3] };
                uint32_t bl0[2] = { tl[0], tl[1] }, bl1[2] = { tl[2], tl[3] };
                mma_bf16(O[g2*2],   Ph[t], bh0);
                mma_bf16(O[g2*2],   Pl[t], bh0);
                mma_bf16(O[g2*2],   Ph[t], bl0);
                mma_bf16(O[g2*2+1], Ph[t], bh1);
                mma_bf16(O[g2*2+1], Pl[t], bh1);
                mma_bf16(O[g2*2+1], Ph[t], bl1);
            }
        }
    }

    // ---- epilogue: normalize + bf16 hi/lo store ----
    const float inv0 = 1.f / l0_, inv1 = 1.f / l1_;
    const int rowA = q0 + wid * 16 + (lid >> 2);
    const int rowB = rowA + 8;
    #pragma unroll
    for (int nf = 0; nf < 8; nf++) {
        const int col = h * HD + nf * 8 + (lid & 3) * 2;
        const size_t offA = (size_t)(b * SEQ + rowA) * DIM + col;
        const size_t offB = (size_t)(b * SEQ + rowB) * DIM + col;
        uint32_t hA, lA, hB, lB;
        split2pack(O[nf][0] * inv0, O[nf][1] * inv0, hA, lA);
        split2pack(O[nf][2] * inv1, O[nf][3] * inv1, hB, lB);
        *(uint32_t*)(oh + offA) = hA;
        *(uint32_t*)(ol + offA) = lA;
        *(uint32_t*)(oh + offB) = hB;
        *(uint32_t*)(ol + offB) = lB;
    }
}

// ---------------------------------------------------------------------------
extern "C" void kernel_launch(void* const* d_in, const int* in_sizes, int n_in,
                              void* d_out, int out_size)
{
    const float* x     = (const float*)d_in[0];
    const float* ln1_g = (const float*)d_in[1];
    const float* ln1_b = (const float*)d_in[2];
    const float* wq = (const float*)d_in[3];
    const float* bq = (const float*)d_in[4];
    const float* wk = (const float*)d_in[5];
    const float* bk = (const float*)d_in[6];
    const float* wv = (const float*)d_in[7];
    const float* bv = (const float*)d_in[8];
    const float* wo = (const float*)d_in[9];
    const float* bo = (const float*)d_in[10];
    const float* w1 = (const float*)d_in[11];
    const float* b1 = (const float*)d_in[12];
    const float* w2 = (const float*)d_in[13];
    const float* b2 = (const float*)d_in[14];
    const float* ln2_g = (const float*)d_in[15];
    const float* ln2_b = (const float*)d_in[16];
    float* out = (float*)d_out;

    bf16 *hh, *hl, *qh, *ql, *kh, *kl, *vh, *vl, *ath, *atl, *h2h, *h2l, *ffh, *ffl;
    bf16 *wqh, *wql, *wkh, *wkl, *wvh, *wvl, *woh, *wol, *w1h, *w1l, *w2h, *w2l;
    float *x1;
    cudaGetSymbolAddress((void**)&hh,  g_hh);  cudaGetSymbolAddress((void**)&hl,  g_hl);
    cudaGetSymbolAddress((void**)&qh,  g_qh);  cudaGetSymbolAddress((void**)&ql,  g_ql);
    cudaGetSymbolAddress((void**)&kh,  g_kh);  cudaGetSymbolAddress((void**)&kl,  g_kl);
    cudaGetSymbolAddress((void**)&vh,  g_vh);  cudaGetSymbolAddress((void**)&vl,  g_vl);
    cudaGetSymbolAddress((void**)&ath, g_ath); cudaGetSymbolAddress((void**)&atl, g_atl);
    cudaGetSymbolAddress((void**)&x1,  g_x1);
    cudaGetSymbolAddress((void**)&h2h, g_h2h); cudaGetSymbolAddress((void**)&h2l, g_h2l);
    cudaGetSymbolAddress((void**)&ffh, g_ffh); cudaGetSymbolAddress((void**)&ffl, g_ffl);
    cudaGetSymbolAddress((void**)&wqh, g_wqh); cudaGetSymbolAddress((void**)&wql, g_wql);
    cudaGetSymbolAddress((void**)&wkh, g_wkh); cudaGetSymbolAddress((void**)&wkl, g_wkl);
    cudaGetSymbolAddress((void**)&wvh, g_wvh); cudaGetSymbolAddress((void**)&wvl, g_wvl);
    cudaGetSymbolAddress((void**)&woh, g_woh); cudaGetSymbolAddress((void**)&wol, g_wol);
    cudaGetSymbolAddress((void**)&w1h, g_w1h); cudaGetSymbolAddress((void**)&w1l, g_w1l);
    cudaGetSymbolAddress((void**)&w2h, g_w2h); cudaGetSymbolAddress((void**)&w2l, g_w2l);

    cudaFuncSetAttribute(mm_tc<0>, cudaFuncAttributeMaxDynamicSharedMemorySize, MM_SMEM);
    cudaFuncSetAttribute(mm_tc<1>, cudaFuncAttributeMaxDynamicSharedMemorySize, MM_SMEM);
    cudaFuncSetAttribute(mm_tc<2>, cudaFuncAttributeMaxDynamicSharedMemorySize, MM_SMEM);
    cudaFuncSetAttribute(mm_tc<3>, cudaFuncAttributeMaxDynamicSharedMemorySize, MM_SMEM);
    cudaFuncSetAttribute(attn_tc,  cudaFuncAttributeMaxDynamicSharedMemorySize, ASMEM);

    // weight transpose + split
    wsplit<<<dim3(DIM/32, DIM/32), 256>>>(wq, wqh, wql, DIM, DIM);
    wsplit<<<dim3(DIM/32, DIM/32), 256>>>(wk, wkh, wkl, DIM, DIM);
    wsplit<<<dim3(DIM/32, DIM/32), 256>>>(wv, wvh, wvl, DIM, DIM);
    wsplit<<<dim3(DIM/32, DIM/32), 256>>>(wo, woh, wol, DIM, DIM);
    wsplit<<<dim3(DFF/32, DIM/32), 256>>>(w1, w1h, w1l, DIM, DFF);
    wsplit<<<dim3(DIM/32, DFF/32), 256>>>(w2, w2h, w2l, DFF, DIM);

    const dim3 gD(DIM / 128, TOK / 128);
    const dim3 gF(DFF / 128, TOK / 128);

    ln_split<<<TOK, 256>>>(x, ln1_g, ln1_b, hh, hl);
    // Q pre-scaled by 1/sqrt(HD) (only consumed by attention)
    mm_tc<3><<<gD, 256, MM_SMEM>>>(hh, hl, wqh, wql, bq, nullptr, nullptr, qh, ql, TOK, DIM, DIM, 0.125f);
    mm_tc<3><<<gD, 256, MM_SMEM>>>(hh, hl, wkh, wkl, bk, nullptr, nullptr, kh, kl, TOK, DIM, DIM, 1.0f);
    mm_tc<3><<<gD, 256, MM_SMEM>>>(hh, hl, wvh, wvl, bv, nullptr, nullptr, vh, vl, TOK, DIM, DIM, 1.0f);
    attn_tc<<<dim3(SEQ / 64, BATCH * NH), 128, ASMEM>>>(qh, ql, kh, kl, vh, vl, ath, atl);
    mm_tc<1><<<gD, 256, MM_SMEM>>>(ath, atl, woh, wol, bo, x, x1, nullptr, nullptr, TOK, DIM, DIM, 1.0f);
    ln_split<<<TOK, 256>>>(x1, ln2_g, ln2_b, h2h, h2l);
    mm_tc<2><<<gF, 256, MM_SMEM>>>(h2h, h2l, w1h, w1l, b1, nullptr, nullptr, ffh, ffl, TOK, DFF, DIM, 1.0f);
    mm_tc<1><<<gD, 256, MM_SMEM>>>(ffh, ffl, w2h, w2l, b2, x1, out, nullptr, nullptr, TOK, DIM, DFF, 1.0f);
}

// round 10
// speedup vs baseline: 2.8149x; 1.0975x over previous
#include <cuda_runtime.h>
#include <cuda_bf16.h>
#include <math.h>
#include <cstdint>

// ---------------------------------------------------------------------------
// Encoder_84413287236054 : fp32 transformer encoder layer on GB300
// Round 10: flash attention v2 — 128-row q-tiles, double-buffered K/V with
// register prefetch, ldmatrix.trans for V (no scalar transpose).
// ---------------------------------------------------------------------------

#define TOK  4096
#define DIM  1024
#define DFF  4096
#define NH   16
#define HD   64
#define SEQ  2048
#define BATCH 2

typedef unsigned long long u64;
typedef __nv_bfloat16 bf16;

// ---- tensor-core primitives (compute_103-legal) ----------------------------
__device__ __forceinline__ uint32_t smem_u32(const void* p) {
    uint32_t a;
    asm("{ .reg .u64 t; cvta.to.shared.u64 t, %1; cvt.u32.u64 %0, t; }" : "=r"(a) : "l"(p));
    return a;
}
__device__ __forceinline__ void ldmx4(uint32_t* r, uint32_t addr) {
    asm volatile("ldmatrix.sync.aligned.m8n8.x4.shared.b16 {%0,%1,%2,%3},[%4];"
        : "=r"(r[0]), "=r"(r[1]), "=r"(r[2]), "=r"(r[3]) : "r"(addr));
}
__device__ __forceinline__ void ldmx4t(uint32_t* r, uint32_t addr) {
    asm volatile("ldmatrix.sync.aligned.m8n8.x4.trans.shared.b16 {%0,%1,%2,%3},[%4];"
        : "=r"(r[0]), "=r"(r[1]), "=r"(r[2]), "=r"(r[3]) : "r"(addr));
}
__device__ __forceinline__ void mma_bf16(float* c, const uint32_t* a, const uint32_t* b) {
    asm volatile("mma.sync.aligned.m16n8k16.row.col.f32.bf16.bf16.f32 "
        "{%0,%1,%2,%3},{%4,%5,%6,%7},{%8,%9},{%0,%1,%2,%3};"
        : "+f"(c[0]), "+f"(c[1]), "+f"(c[2]), "+f"(c[3])
        : "r"(a[0]), "r"(a[1]), "r"(a[2]), "r"(a[3]), "r"(b[0]), "r"(b[1]));
}

__device__ __forceinline__ void split1(float x, bf16& h, bf16& l) {
    h = __float2bfloat16(x);
    l = __float2bfloat16(x - __bfloat162float(h));
}
__device__ __forceinline__ uint32_t packbf2(bf16 a, bf16 b) {
    __nv_bfloat162 t = __halves2bfloat162(a, b);
    return *(uint32_t*)&t;
}
__device__ __forceinline__ void split2pack(float a, float b, uint32_t& hp, uint32_t& lp) {
    bf16 ha, la, hb, lb;
    split1(a, ha, la); split1(b, hb, lb);
    hp = packbf2(ha, hb); lp = packbf2(la, lb);
}

// ---------------- scratch (allocation-free) ---------------------------------
__device__ bf16  g_hh [TOK * DIM], g_hl [TOK * DIM];
__device__ bf16  g_qh [TOK * DIM], g_ql [TOK * DIM];
__device__ bf16  g_kh [TOK * DIM], g_kl [TOK * DIM];
__device__ bf16  g_vh [TOK * DIM], g_vl [TOK * DIM];
__device__ bf16  g_ath[TOK * DIM], g_atl[TOK * DIM];
__device__ float g_x1 [TOK * DIM];
__device__ bf16  g_h2h[TOK * DIM], g_h2l[TOK * DIM];
__device__ bf16  g_ffh[TOK * DFF], g_ffl[TOK * DFF];
__device__ bf16 g_wqh[DIM * DIM], g_wql[DIM * DIM];
__device__ bf16 g_wkh[DIM * DIM], g_wkl[DIM * DIM];
__device__ bf16 g_wvh[DIM * DIM], g_wvl[DIM * DIM];
__device__ bf16 g_woh[DIM * DIM], g_wol[DIM * DIM];
__device__ bf16 g_w1h[DFF * DIM], g_w1l[DFF * DIM];
__device__ bf16 g_w2h[DIM * DFF], g_w2l[DIM * DFF];

// ---------------------------------------------------------------------------
// Weight transpose + hi/lo split: W[K,N] fp32 -> Th,Tl [N,K] bf16
// ---------------------------------------------------------------------------
__global__ __launch_bounds__(256) void wsplit(
    const float* __restrict__ W, bf16* __restrict__ Th, bf16* __restrict__ Tl,
    int K, int N)
{
    __shared__ float t[32][33];
    const int n0 = blockIdx.x * 32, k0 = blockIdx.y * 32;
    const int tx = threadIdx.x & 31, ty = threadIdx.x >> 5;
    #pragma unroll
    for (int i = ty; i < 32; i += 8)
        t[i][tx] = W[(size_t)(k0 + i) * N + n0 + tx];
    __syncthreads();
    #pragma unroll
    for (int i = ty; i < 32; i += 8) {
        const float x = t[tx][i];
        bf16 h, l; split1(x, h, l);
        Th[(size_t)(n0 + i) * K + k0 + tx] = h;
        Tl[(size_t)(n0 + i) * K + k0 + tx] = l;
    }
}

// ---------------------------------------------------------------------------
// LayerNorm -> bf16 hi/lo
// ---------------------------------------------------------------------------
__global__ __launch_bounds__(256) void ln_split(
    const float* __restrict__ x, const float* __restrict__ g,
    const float* __restrict__ b, bf16* __restrict__ oh, bf16* __restrict__ ol)
{
    const int row = blockIdx.x;
    const int t = threadIdx.x;
    const float4 v = ((const float4*)(x + (size_t)row * DIM))[t];

    float s  = v.x + v.y + v.z + v.w;
    float ss = v.x*v.x + v.y*v.y + v.z*v.z + v.w*v.w;
    #pragma unroll
    for (int o = 16; o; o >>= 1) {
        s  += __shfl_xor_sync(0xffffffffu, s,  o);
        ss += __shfl_xor_sync(0xffffffffu, ss, o);
    }
    __shared__ float sm[8], sm2[8];
    if ((t & 31) == 0) { sm[t >> 5] = s; sm2[t >> 5] = ss; }
    __syncthreads();
    float ts = 0.f, tss = 0.f;
    #pragma unroll
    for (int i = 0; i < 8; i++) { ts += sm[i]; tss += sm2[i]; }

    const float mu   = ts * (1.0f / DIM);
    const float rstd = rsqrtf(tss * (1.0f / DIM) - mu * mu + 1e-5f);
    const float4 gv = ((const float4*)g)[t];
    const float4 bv = ((const float4*)b)[t];
    float y[4];
    y[0] = (v.x - mu) * rstd * gv.x + bv.x;
    y[1] = (v.y - mu) * rstd * gv.y + bv.y;
    y[2] = (v.z - mu) * rstd * gv.z + bv.z;
    y[3] = (v.w - mu) * rstd * gv.w + bv.w;
    uint32_t hp0, lp0, hp1, lp1;
    split2pack(y[0], y[1], hp0, lp0);
    split2pack(y[2], y[3], hp1, lp1);
    *(uint2*)(oh + (size_t)row * DIM + t * 4) = make_uint2(hp0, hp1);
    *(uint2*)(ol + (size_t)row * DIM + t * 4) = make_uint2(lp0, lp1);
}

// ---------------------------------------------------------------------------
// Tensor-core GEMM (unchanged from R9 WIN)
// ---------------------------------------------------------------------------
#define ARR_B  10240u
#define BUFSZ  40960u
#define MM_SMEM (2u * BUFSZ)

template<int EPI>
__global__ __launch_bounds__(256, 1) void mm_tc(
    const bf16* __restrict__ Ah, const bf16* __restrict__ Al,
    const bf16* __restrict__ Bh, const bf16* __restrict__ Bl,
    const float* __restrict__ bias, const float* __restrict__ res,
    float* __restrict__ C, bf16* __restrict__ Ch, bf16* __restrict__ Cl,
    int M, int N, int K, float oscale)
{
    extern __shared__ char smem[];
    const uint32_t sb = smem_u32(smem);
    const int tid = threadIdx.x, wid = tid >> 5, lid = tid & 31;
    const int wm = wid & 1, wn = wid >> 1;
    const int m0 = blockIdx.y * 128, n0 = blockIdx.x * 128;

    const int r0_ = tid >> 2, c0_ = tid & 3;
    const int r1_ = r0_ + 64;

    const bf16* srcs[4] = { Ah, Al, Bh, Bl };
    const int   base4[4] = { m0, m0, n0, n0 };

    auto fetch = [&](int kt, uint4* pf) {
        #pragma unroll
        for (int a = 0; a < 4; a++) {
            const bf16* s = srcs[a] + (size_t)base4[a] * K + kt * 32;
            pf[a * 2 + 0] = *(const uint4*)(s + (size_t)r0_ * K + c0_ * 8);
            pf[a * 2 + 1] = *(const uint4*)(s + (size_t)r1_ * K + c0_ * 8);
        }
    };
    auto commit = [&](int buf, const uint4* pf) {
        char* bb = smem + buf * BUFSZ;
        #pragma unroll
        for (int a = 0; a < 4; a++) {
            *(uint4*)(bb + a * ARR_B + r0_ * 80 + c0_ * 16) = pf[a * 2 + 0];
            *(uint4*)(bb + a * ARR_B + r1_ * 80 + c0_ * 16) = pf[a * 2 + 1];
        }
    };

    float acc[4][4][4] = {};

    const int arow = wm * 64 + (lid & 7) + ((lid >> 3) & 1) * 8;
    const uint32_t acolb = ((lid >> 4) & 1) * 16;
    const int brow = wn * 32 + (lid & 7) + ((lid >> 4) & 1) * 8;
    const uint32_t bcolb = ((lid >> 3) & 1) * 16;

    {
        uint4 pf[8];
        fetch(0, pf);
        commit(0, pf);
    }
    __syncthreads();

    const int nk = K >> 5;
    for (int kt = 0; kt < nk; kt++) {
        const int buf = kt & 1;
        uint4 pf[8];
        if (kt + 1 < nk) fetch(kt + 1, pf);

        const uint32_t bb = sb + buf * BUFSZ;
        #pragma unroll
        for (int kh = 0; kh < 2; kh++) {
            uint32_t ah[4][4], al[4][4], bh[4][2], bl[4][2];
            #pragma unroll
            for (int mf = 0; mf < 4; mf++) {
                const uint32_t ad = bb + (arow + mf * 16) * 80 + acolb + kh * 32;
                ldmx4(ah[mf], ad);
                ldmx4(al[mf], ad + ARR_B);
            }
            #pragma unroll
            for (int g2 = 0; g2 < 2; g2++) {
                const uint32_t bd = bb + 2 * ARR_B + (brow + g2 * 16) * 80 + bcolb + kh * 32;
                uint32_t t[4];
                ldmx4(t, bd);
                bh[g2*2][0] = t[0]; bh[g2*2][1] = t[1];
                bh[g2*2+1][0] = t[2]; bh[g2*2+1][1] = t[3];
                ldmx4(t, bd + ARR_B);
                bl[g2*2][0] = t[0]; bl[g2*2][1] = t[1];
                bl[g2*2+1][0] = t[2]; bl[g2*2+1][1] = t[3];
            }
            #pragma unroll
            for (int mf = 0; mf < 4; mf++)
                #pragma unroll
                for (int nf = 0; nf < 4; nf++) {
                    mma_bf16(acc[mf][nf], ah[mf], bh[nf]);
                    mma_bf16(acc[mf][nf], ah[mf], bl[nf]);
                    mma_bf16(acc[mf][nf], al[mf], bh[nf]);
                }
        }

        if (kt + 1 < nk) {
            commit(buf ^ 1, pf);
            __syncthreads();
        }
    }

    // ---------------- epilogue ----------------
    #pragma unroll
    for (int mf = 0; mf < 4; mf++) {
        const int rowA = m0 + wm * 64 + mf * 16 + (lid >> 2);
        const int rowB = rowA + 8;
        #pragma unroll
        for (int nf = 0; nf < 4; nf++) {
            const int col = n0 + wn * 32 + nf * 8 + (lid & 3) * 2;
            const float2 b2 = *(const float2*)(bias + col);
            float v0 = acc[mf][nf][0] + b2.x;
            float v1 = acc[mf][nf][1] + b2.y;
            float v2 = acc[mf][nf][2] + b2.x;
            float v3 = acc[mf][nf][3] + b2.y;
            const size_t offA = (size_t)rowA * N + col;
            const size_t offB = (size_t)rowB * N + col;
            if (EPI == 1) {
                const float2 rA = *(const float2*)(res + offA);
                const float2 rB = *(const float2*)(res + offB);
                v0 += rA.x; v1 += rA.y; v2 += rB.x; v3 += rB.y;
            }
            if (EPI == 2 || EPI == 3) {
                if (EPI == 2) {
                    v0 = v0 * normcdff(v0); v1 = v1 * normcdff(v1);
                    v2 = v2 * normcdff(v2); v3 = v3 * normcdff(v3);
                } else {
                    v0 *= oscale; v1 *= oscale; v2 *= oscale; v3 *= oscale;
                }
                uint32_t hA, lA, hB, lB;
                split2pack(v0, v1, hA, lA);
                split2pack(v2, v3, hB, lB);
                *(uint32_t*)(Ch + offA) = hA;
                *(uint32_t*)(Cl + offA) = lA;
                *(uint32_t*)(Ch + offB) = hB;
                *(uint32_t*)(Cl + offB) = lB;
            } else {
                *(float2*)(C + offA) = make_float2(v0, v1);
                *(float2*)(C + offB) = make_float2(v2, v3);
            }
        }
    }
}

// ---------------------------------------------------------------------------
// Flash attention v2. Grid (SEQ/128, B*NH). Block 256 = 8 warps; warp = 16 q.
// Smem: QH QL (128x144B) | 2 x [KH KL VH VL] (64x144B each), double-buffered.
// K and V both row-major [kv][hd]; V B-frags via ldmatrix.trans.
// ---------------------------------------------------------------------------
#define AQ_B   18432u                   // 128 * 144
#define AKV_B  9216u                    // 64 * 144
#define KV0    (2u * AQ_B)              // 36864
#define KVBUF  (4u * AKV_B)             // 36864 per buffer
#define ASMEM  (KV0 + 2u * KVBUF)       // 110592

__global__ __launch_bounds__(256, 1) void attn_tc(
    const bf16* __restrict__ qh, const bf16* __restrict__ ql,
    const bf16* __restrict__ kh, const bf16* __restrict__ kl,
    const bf16* __restrict__ vh, const bf16* __restrict__ vl,
    bf16* __restrict__ oh, bf16* __restrict__ ol)
{
    extern __shared__ char smem[];
    const uint32_t sb = smem_u32(smem);
    const int tid = threadIdx.x, wid = tid >> 5, lid = tid & 31;
    const int bh_ = blockIdx.y;
    const int b = bh_ >> 4, h = bh_ & 15;
    const int q0 = blockIdx.x * 128;
    const size_t base = (size_t)(b * SEQ) * DIM + h * HD;

    // ---- K/V fetch/commit (register prefetch, double-buffered smem) ----
    auto fetchKV = [&](int kt, uint4* pf) {
        const size_t rowb = base + (size_t)(kt * 64) * DIM;
        #pragma unroll
        for (int u = 0; u < 2; u++) {
            const int idx = u * 256 + tid;
            const int r = idx >> 3, c8 = idx & 7;
            const size_t gp = rowb + (size_t)r * DIM + c8 * 8;
            pf[u*4+0] = *(const uint4*)(kh + gp);
            pf[u*4+1] = *(const uint4*)(kl + gp);
            pf[u*4+2] = *(const uint4*)(vh + gp);
            pf[u*4+3] = *(const uint4*)(vl + gp);
        }
    };
    auto commitKV = [&](int buf, const uint4* pf) {
        char* bb = smem + KV0 + buf * KVBUF;
        #pragma unroll
        for (int u = 0; u < 2; u++) {
            const int idx = u * 256 + tid;
            const int r = idx >> 3, c8 = idx & 7;
            *(uint4*)(bb + 0*AKV_B + r * 144 + c8 * 16) = pf[u*4+0];
            *(uint4*)(bb + 1*AKV_B + r * 144 + c8 * 16) = pf[u*4+1];
            *(uint4*)(bb + 2*AKV_B + r * 144 + c8 * 16) = pf[u*4+2];
            *(uint4*)(bb + 3*AKV_B + r * 144 + c8 * 16) = pf[u*4+3];
        }
    };

    // ---- stage Q tile (128 rows) + first K/V tile ----
    #pragma unroll
    for (int it = 0; it < 4; it++) {
        const int idx = it * 256 + tid;
        const int r = idx >> 3, c8 = idx & 7;
        const size_t gp = base + (size_t)(q0 + r) * DIM + c8 * 8;
        *(uint4*)(smem + 0      + r * 144 + c8 * 16) = *(const uint4*)(qh + gp);
        *(uint4*)(smem + AQ_B   + r * 144 + c8 * 16) = *(const uint4*)(ql + gp);
    }
    {
        uint4 pf0[8];
        fetchKV(0, pf0);
        commitKV(0, pf0);
    }
    __syncthreads();

    // ---- per-warp Q A-fragments ----
    uint32_t Qh_[4][4], Ql_[4][4];
    const int arow = wid * 16 + (lid & 7) + ((lid >> 3) & 1) * 8;
    const uint32_t acol = ((lid >> 4) & 1) * 16;
    #pragma unroll
    for (int ks = 0; ks < 4; ks++) {
        const uint32_t ad = sb + arow * 144 + acol + ks * 32;
        ldmx4(Qh_[ks], ad);
        ldmx4(Ql_[ks], ad + AQ_B);
    }

    float O[8][4] = {};
    float m0_ = -1e30f, m1_ = -1e30f, l0_ = 0.f, l1_ = 0.f;

    // K B-frag lane addressing (row-major [kv][hd], non-trans)
    const int brow = (lid & 7) + ((lid >> 4) & 1) * 8;
    const uint32_t bcol = ((lid >> 3) & 1) * 16;
    // V B-frag lane addressing (row-major [kv][hd], trans)
    const int vrow = (lid & 7) + ((lid >> 3) & 1) * 8;
    const uint32_t vcole = ((lid >> 4) & 1) * 8;

    const int NT = SEQ / 64;
    for (int kt = 0; kt < NT; kt++) {
        const int buf = kt & 1;
        uint4 pf[8];
        if (kt + 1 < NT) fetchKV(kt + 1, pf);

        const uint32_t kvb = sb + KV0 + buf * KVBUF;

        // ---- scores S = Q K^T (3-MMA hi/lo) ----
        float S[8][4] = {};
        #pragma unroll
        for (int ks = 0; ks < 4; ks++) {
            #pragma unroll
            for (int g2 = 0; g2 < 4; g2++) {
                const uint32_t bd = kvb + (brow + g2 * 16) * 144 + bcol + ks * 32;
                uint32_t th[4], tl[4];
                ldmx4(th, bd);
                ldmx4(tl, bd + AKV_B);
                uint32_t bh0[2] = { th[0], th[1] }, bh1[2] = { th[2], th[3] };
                uint32_t bl0[2] = { tl[0], tl[1] }, bl1[2] = { tl[2], tl[3] };
                mma_bf16(S[g2*2],   Qh_[ks], bh0);
                mma_bf16(S[g2*2],   Qh_[ks], bl0);
                mma_bf16(S[g2*2],   Ql_[ks], bh0);
                mma_bf16(S[g2*2+1], Qh_[ks], bh1);
                mma_bf16(S[g2*2+1], Qh_[ks], bl1);
                mma_bf16(S[g2*2+1], Ql_[ks], bh1);
            }
        }

        // ---- online softmax ----
        float rm0 = -1e30f, rm1 = -1e30f;
        #pragma unroll
        for (int nf = 0; nf < 8; nf++) {
            rm0 = fmaxf(rm0, fmaxf(S[nf][0], S[nf][1]));
            rm1 = fmaxf(rm1, fmaxf(S[nf][2], S[nf][3]));
        }
        rm0 = fmaxf(rm0, __shfl_xor_sync(0xffffffffu, rm0, 1));
        rm0 = fmaxf(rm0, __shfl_xor_sync(0xffffffffu, rm0, 2));
        rm1 = fmaxf(rm1, __shfl_xor_sync(0xffffffffu, rm1, 1));
        rm1 = fmaxf(rm1, __shfl_xor_sync(0xffffffffu, rm1, 2));
        const float mn0 = fmaxf(m0_, rm0), mn1 = fmaxf(m1_, rm1);
        const float c0 = __expf(m0_ - mn0), c1 = __expf(m1_ - mn1);
        m0_ = mn0; m1_ = mn1;

        float rs0 = 0.f, rs1 = 0.f;
        #pragma unroll
        for (int nf = 0; nf < 8; nf++) {
            S[nf][0] = __expf(S[nf][0] - mn0);
            S[nf][1] = __expf(S[nf][1] - mn0);
            S[nf][2] = __expf(S[nf][2] - mn1);
            S[nf][3] = __expf(S[nf][3] - mn1);
            rs0 += S[nf][0] + S[nf][1];
            rs1 += S[nf][2] + S[nf][3];
        }
        rs0 += __shfl_xor_sync(0xffffffffu, rs0, 1);
        rs0 += __shfl_xor_sync(0xffffffffu, rs0, 2);
        rs1 += __shfl_xor_sync(0xffffffffu, rs1, 1);
        rs1 += __shfl_xor_sync(0xffffffffu, rs1, 2);
        l0_ = l0_ * c0 + rs0;
        l1_ = l1_ * c1 + rs1;
        #pragma unroll
        for (int nf = 0; nf < 8; nf++) {
            O[nf][0] *= c0; O[nf][1] *= c0;
            O[nf][2] *= c1; O[nf][3] *= c1;
        }

        // ---- P fragments (hi/lo) from S ----
        uint32_t Ph[4][4], Pl[4][4];
        #pragma unroll
        for (int t = 0; t < 4; t++) {
            split2pack(S[2*t][0],   S[2*t][1],   Ph[t][0], Pl[t][0]);
            split2pack(S[2*t][2],   S[2*t][3],   Ph[t][1], Pl[t][1]);
            split2pack(S[2*t+1][0], S[2*t+1][1], Ph[t][2], Pl[t][2]);
            split2pack(S[2*t+1][2], S[2*t+1][3], Ph[t][3], Pl[t][3]);
        }

        // ---- O += P V (3-MMA hi/lo), V row-major via ldmatrix.trans ----
        #pragma unroll
        for (int t = 0; t < 4; t++) {          // kv k-steps (16 each)
            #pragma unroll
            for (int g2 = 0; g2 < 4; g2++) {   // hd n-groups of 16
                const uint32_t vd = kvb + 2*AKV_B +
                    (t * 16 + vrow) * 144 + (g2 * 16 + vcole) * 2;
                uint32_t th[4], tl[4];
                ldmx4t(th, vd);
                ldmx4t(tl, vd + AKV_B);
                uint32_t bh0[2] = { th[0], th[1] }, bh1[2] = { th[2], th[3] };
                uint32_t bl0[2] = { tl[0], tl[1] }, bl1[2] = { tl[2], tl[3] };
                mma_bf16(O[g2*2],   Ph[t], bh0);
                mma_bf16(O[g2*2],   Pl[t], bh0);
                mma_bf16(O[g2*2],   Ph[t], bl0);
                mma_bf16(O[g2*2+1], Ph[t], bh1);
                mma_bf16(O[g2*2+1], Pl[t], bh1);
                mma_bf16(O[g2*2+1], Ph[t], bl1);
            }
        }

        if (kt + 1 < NT) {
            commitKV(buf ^ 1, pf);
            __syncthreads();
        }
    }

    // ---- epilogue: normalize + bf16 hi/lo store ----
    const float inv0 = 1.f / l0_, inv1 = 1.f / l1_;
    const int rowA = q0 + wid * 16 + (lid >> 2);
    const int rowB = rowA + 8;
    #pragma unroll
    for (int nf = 0; nf < 8; nf++) {
        const int col = h * HD + nf * 8 + (lid & 3) * 2;
        const size_t offA = (size_t)(b * SEQ + rowA) * DIM + col;
        const size_t offB = (size_t)(b * SEQ + rowB) * DIM + col;
        uint32_t hA, lA, hB, lB;
        split2pack(O[nf][0] * inv0, O[nf][1] * inv0, hA, lA);
        split2pack(O[nf][2] * inv1, O[nf][3] * inv1, hB, lB);
        *(uint32_t*)(oh + offA) = hA;
        *(uint32_t*)(ol + offA) = lA;
        *(uint32_t*)(oh + offB) = hB;
        *(uint32_t*)(ol + offB) = lB;
    }
}

// ---------------------------------------------------------------------------
extern "C" void kernel_launch(void* const* d_in, const int* in_sizes, int n_in,
                              void* d_out, int out_size)
{
    const float* x     = (const float*)d_in[0];
    const float* ln1_g = (const float*)d_in[1];
    const float* ln1_b = (const float*)d_in[2];
    const float* wq = (const float*)d_in[3];
    const float* bq = (const float*)d_in[4];
    const float* wk = (const float*)d_in[5];
    const float* bk = (const float*)d_in[6];
    const float* wv = (const float*)d_in[7];
    const float* bv = (const float*)d_in[8];
    const float* wo = (const float*)d_in[9];
    const float* bo = (const float*)d_in[10];
    const float* w1 = (const float*)d_in[11];
    const float* b1 = (const float*)d_in[12];
    const float* w2 = (const float*)d_in[13];
    const float* b2 = (const float*)d_in[14];
    const float* ln2_g = (const float*)d_in[15];
    const float* ln2_b = (const float*)d_in[16];
    float* out = (float*)d_out;

    bf16 *hh, *hl, *qh, *ql, *kh, *kl, *vh, *vl, *ath, *atl, *h2h, *h2l, *ffh, *ffl;
    bf16 *wqh, *wql, *wkh, *wkl, *wvh, *wvl, *woh, *wol, *w1h, *w1l, *w2h, *w2l;
    float *x1;
    cudaGetSymbolAddress((void**)&hh,  g_hh);  cudaGetSymbolAddress((void**)&hl,  g_hl);
    cudaGetSymbolAddress((void**)&qh,  g_qh);  cudaGetSymbolAddress((void**)&ql,  g_ql);
    cudaGetSymbolAddress((void**)&kh,  g_kh);  cudaGetSymbolAddress((void**)&kl,  g_kl);
    cudaGetSymbolAddress((void**)&vh,  g_vh);  cudaGetSymbolAddress((void**)&vl,  g_vl);
    cudaGetSymbolAddress((void**)&ath, g_ath); cudaGetSymbolAddress((void**)&atl, g_atl);
    cudaGetSymbolAddress((void**)&x1,  g_x1);
    cudaGetSymbolAddress((void**)&h2h, g_h2h); cudaGetSymbolAddress((void**)&h2l, g_h2l);
    cudaGetSymbolAddress((void**)&ffh, g_ffh); cudaGetSymbolAddress((void**)&ffl, g_ffl);
    cudaGetSymbolAddress((void**)&wqh, g_wqh); cudaGetSymbolAddress((void**)&wql, g_wql);
    cudaGetSymbolAddress((void**)&wkh, g_wkh); cudaGetSymbolAddress((void**)&wkl, g_wkl);
    cudaGetSymbolAddress((void**)&wvh, g_wvh); cudaGetSymbolAddress((void**)&wvl, g_wvl);
    cudaGetSymbolAddress((void**)&woh, g_woh); cudaGetSymbolAddress((void**)&wol, g_wol);
    cudaGetSymbolAddress((void**)&w1h, g_w1h); cudaGetSymbolAddress((void**)&w1l, g_w1l);
    cudaGetSymbolAddress((void**)&w2h, g_w2h); cudaGetSymbolAddress((void**)&w2l, g_w2l);

    cudaFuncSetAttribute(mm_tc<0>, cudaFuncAttributeMaxDynamicSharedMemorySize, MM_SMEM);
    cudaFuncSetAttribute(mm_tc<1>, cudaFuncAttributeMaxDynamicSharedMemorySize, MM_SMEM);
    cudaFuncSetAttribute(mm_tc<2>, cudaFuncAttributeMaxDynamicSharedMemorySize, MM_SMEM);
    cudaFuncSetAttribute(mm_tc<3>, cudaFuncAttributeMaxDynamicSharedMemorySize, MM_SMEM);
    cudaFuncSetAttribute(attn_tc,  cudaFuncAttributeMaxDynamicSharedMemorySize, ASMEM);

    // weight transpose + split
    wsplit<<<dim3(DIM/32, DIM/32), 256>>>(wq, wqh, wql, DIM, DIM);
    wsplit<<<dim3(DIM/32, DIM/32), 256>>>(wk, wkh, wkl, DIM, DIM);
    wsplit<<<dim3(DIM/32, DIM/32), 256>>>(wv, wvh, wvl, DIM, DIM);
    wsplit<<<dim3(DIM/32, DIM/32), 256>>>(wo, woh, wol, DIM, DIM);
    wsplit<<<dim3(DFF/32, DIM/32), 256>>>(w1, w1h, w1l, DIM, DFF);
    wsplit<<<dim3(DIM/32, DFF/32), 256>>>(w2, w2h, w2l, DFF, DIM);

    const dim3 gD(DIM / 128, TOK / 128);
    const dim3 gF(DFF / 128, TOK / 128);

    ln_split<<<TOK, 256>>>(x, ln1_g, ln1_b, hh, hl);
    mm_tc<3><<<gD, 256, MM_SMEM>>>(hh, hl, wqh, wql, bq, nullptr, nullptr, qh, ql, TOK, DIM, DIM, 0.125f);
    mm_tc<3><<<gD, 256, MM_SMEM>>>(hh, hl, wkh, wkl, bk, nullptr, nullptr, kh, kl, TOK, DIM, DIM, 1.0f);
    mm_tc<3><<<gD, 256, MM_SMEM>>>(hh, hl, wvh, wvl, bv, nullptr, nullptr, vh, vl, TOK, DIM, DIM, 1.0f);
    attn_tc<<<dim3(SEQ / 128, BATCH * NH), 256, ASMEM>>>(qh, ql, kh, kl, vh, vl, ath, atl);
    mm_tc<1><<<gD, 256, MM_SMEM>>>(ath, atl, woh, wol, bo, x, x1, nullptr, nullptr, TOK, DIM, DIM, 1.0f);
    ln_split<<<TOK, 256>>>(x1, ln2_g, ln2_b, h2h, h2l);
    mm_tc<2><<<gF, 256, MM_SMEM>>>(h2h, h2l, w1h, w1l, b1, nullptr, nullptr, ffh, ffl, TOK, DFF, DIM, 1.0f);
    mm_tc<1><<<gD, 256, MM_SMEM>>>(ffh, ffl, w2h, w2l, b2, x1, out, nullptr, nullptr, TOK, DIM, DFF, 1.0f);
}